// round 10
// baseline (speedup 1.0000x reference)
#include <cuda_runtime.h>
#include <cuda_bf16.h>
#include <math.h>
#include <stdint.h>

#define Bv   64
#define Nv   256
#define Din  16
#define Hv   128
#define Lv   6
#define DFFv 2048
#define HEADSv 8
#define DHv  16
#define TOURLEN 16
#define LSCALE 0.08838834764831845f   /* H^-0.5 */

#define MTOK (Bv*Nv)                  /* 16384 */
#define HS_STRIDE ((size_t)MTOK*Hv)   /* activation plane stride, H wide */
#define FF_STRIDE ((size_t)MTOK*DFFv) /* ff plane stride */

// -------------------- device scratch --------------------
__device__ float g_h[MTOK*Hv];
__device__ float g_tmp[MTOK*3*Hv];        // qkv f32 / gemm tmp
__device__ float g_k[MTOK*Hv];
__device__ float g_M[MTOK*Hv];
__device__ float g_baseQ[MTOK*Hv];
__device__ float g_graph[Bv*Hv];
__device__ float g_gq[Bv*Hv];
__device__ float g_W1q[Hv*Hv];
__device__ float g_W2q[Hv*Hv];
__device__ float g_W3q[Hv*Hv];
__device__ float g_bq2[Hv];
__device__ float g_baseL[Bv*Nv*Nv];
__device__ float g_cross[Bv*Nv*Nv];

// split-3 bf16 planes
__device__ __nv_bfloat16 g_hs[3*MTOK*Hv];                 // h planes
__device__ __nv_bfloat16 g_atts[3*MTOK*Hv];               // attention-out planes
__device__ __nv_bfloat16 g_ffs[(size_t)3*MTOK*DFFv];      // ff planes (201MB)
// transposed split weights, per layer: [l][plane][N*K]
__device__ __nv_bfloat16 g_wqkvt[(size_t)Lv*3*(3*Hv)*Hv];
__device__ __nv_bfloat16 g_wot[(size_t)Lv*3*Hv*Hv];
__device__ __nv_bfloat16 g_w1t[(size_t)Lv*3*DFFv*Hv];
__device__ __nv_bfloat16 g_w2t[(size_t)Lv*3*Hv*DFFv];

// -------------------- split3 --------------------
__device__ __forceinline__ void split3(float v, __nv_bfloat16& b0,
                                       __nv_bfloat16& b1, __nv_bfloat16& b2) {
    b0 = __float2bfloat16(v);
    float r = v - __bfloat162float(b0);
    b1 = __float2bfloat16(r);
    float r2 = r - __bfloat162float(b1);
    b2 = __float2bfloat16(r2);
}
__device__ __forceinline__ void mma16(float* d, const uint32_t* a, uint32_t b0, uint32_t b1) {
    asm volatile(
        "mma.sync.aligned.m16n8k16.row.col.f32.bf16.bf16.f32 "
        "{%0,%1,%2,%3}, {%4,%5,%6,%7}, {%8,%9}, {%0,%1,%2,%3};"
        : "+f"(d[0]), "+f"(d[1]), "+f"(d[2]), "+f"(d[3])
        : "r"(a[0]), "r"(a[1]), "r"(a[2]), "r"(a[3]), "r"(b0), "r"(b1));
}

// -------------------- weight prep: W[K][N] -> 3 planes [N][K] --------------------
__global__ __launch_bounds__(256)
void wprep(const float* __restrict__ W, __nv_bfloat16* __restrict__ out, int K, int N)
{
    int idx = blockIdx.x * 256 + threadIdx.x;
    if (idx >= K * N) return;
    int n = idx / K, k = idx - n * K;
    float v = W[(size_t)k * N + n];
    __nv_bfloat16 b0, b1, b2;
    split3(v, b0, b1, b2);
    size_t ps = (size_t)N * K;
    out[idx] = b0; out[ps + idx] = b1; out[2 * ps + idx] = b2;
}

// -------------------- split h -> planes --------------------
__global__ __launch_bounds__(256)
void split_act(const float* __restrict__ in, __nv_bfloat16* __restrict__ out, size_t n, size_t ps)
{
    size_t idx = (size_t)blockIdx.x * 256 + threadIdx.x;
    if (idx >= n) return;
    __nv_bfloat16 b0, b1, b2;
    split3(in[idx], b0, b1, b2);
    out[idx] = b0; out[ps + idx] = b1; out[2 * ps + idx] = b2;
}

// ============================================================================
// mma_gemm: C[128x64 tile] = A @ B^T over pre-split bf16 planes.
// A planes: [M][K] row-major, plane stride strA. B planes: [N][K], stride strB.
// Unbiased accumulation (R9-proven): main a0b0 via mma(C=0)+FADD; 5 corrections chained.
// EPI: 0 -> f32 out, 2 -> bias + f32 out, 1 -> bias+relu+split3 -> 3 bf16 planes.
// ============================================================================
#define APLANE 5120                /* 128 * 40 halfwords */
#define BPLANE 2560                /*  64 * 40 */
#define SMB_BYTES ((3*APLANE + 3*BPLANE) * 2)  /* 46080 */

template<int EPI>
__global__ __launch_bounds__(256, 2)
void mma_gemm(const __nv_bfloat16* __restrict__ A, size_t strA,
              const __nv_bfloat16* __restrict__ B, size_t strB,
              const float* __restrict__ bias,
              float* __restrict__ Cf, __nv_bfloat16* __restrict__ Cp, size_t strCp,
              int K, int ldc)
{
    extern __shared__ __nv_bfloat16 smh[];
    __nv_bfloat16* smA = smh;
    __nv_bfloat16* smB = smh + 3 * APLANE;

    const int tid = threadIdx.x;
    const int lane = tid & 31;
    const int wid = tid >> 5;
    const int wm = wid & 1;
    const int wn = wid >> 1;
    const int tg = lane >> 2;
    const int tq = lane & 3;
    const int bm = blockIdx.y * 128, bn = blockIdx.x * 64;

    float accR[4][2][4];
    float accC[4][2][4];
    #pragma unroll
    for (int i = 0; i < 4; i++)
        #pragma unroll
        for (int j = 0; j < 2; j++)
            #pragma unroll
            for (int e = 0; e < 4; e++) { accR[i][j][e] = 0.f; accC[i][j][e] = 0.f; }

    for (int kc = 0; kc < K; kc += 32) {
        // ---- A: 3 planes x 128 rows x 32 k, uint4 copies (6 per thread)
        #pragma unroll
        for (int it = 0; it < 6; it++) {
            int lin = tid + it * 256;
            int p = lin >> 9, rem = lin & 511;
            int r = rem >> 2, kq = (rem & 3) << 3;
            *(uint4*)&smA[p * APLANE + r * 40 + kq] =
                *(const uint4*)&A[p * strA + (size_t)(bm + r) * K + kc + kq];
        }
        // ---- B: 3 planes x 64 rows x 32 k (3 per thread)
        #pragma unroll
        for (int it = 0; it < 3; it++) {
            int lin = tid + it * 256;
            int p = lin >> 8, rem = lin & 255;
            int n = rem >> 2, kq = (rem & 3) << 3;
            *(uint4*)&smB[p * BPLANE + n * 40 + kq] =
                *(const uint4*)&B[p * strB + (size_t)(bn + n) * K + kc + kq];
        }
        __syncthreads();

        #pragma unroll
        for (int ks = 0; ks < 32; ks += 16) {
            #pragma unroll
            for (int mt = 0; mt < 4; mt++) {
                const int r = wm * 64 + mt * 16 + tg;
                uint32_t a0[4], a1[4], a2[4];
                {
                    const int i00 = r * 40 + ks + 2 * tq;
                    const int i10 = (r + 8) * 40 + ks + 2 * tq;
                    a0[0] = *(const uint32_t*)&smA[i00];
                    a0[1] = *(const uint32_t*)&smA[i10];
                    a0[2] = *(const uint32_t*)&smA[i00 + 8];
                    a0[3] = *(const uint32_t*)&smA[i10 + 8];
                    a1[0] = *(const uint32_t*)&smA[APLANE + i00];
                    a1[1] = *(const uint32_t*)&smA[APLANE + i10];
                    a1[2] = *(const uint32_t*)&smA[APLANE + i00 + 8];
                    a1[3] = *(const uint32_t*)&smA[APLANE + i10 + 8];
                    a2[0] = *(const uint32_t*)&smA[2 * APLANE + i00];
                    a2[1] = *(const uint32_t*)&smA[2 * APLANE + i10];
                    a2[2] = *(const uint32_t*)&smA[2 * APLANE + i00 + 8];
                    a2[3] = *(const uint32_t*)&smA[2 * APLANE + i10 + 8];
                }
                #pragma unroll
                for (int nt = 0; nt < 2; nt++) {
                    const int n = wn * 16 + nt * 8 + tg;
                    const int j0 = n * 40 + ks + 2 * tq;
                    uint32_t b0l = *(const uint32_t*)&smB[j0];
                    uint32_t b0h = *(const uint32_t*)&smB[j0 + 8];
                    uint32_t b1l = *(const uint32_t*)&smB[BPLANE + j0];
                    uint32_t b1h = *(const uint32_t*)&smB[BPLANE + j0 + 8];
                    uint32_t b2l = *(const uint32_t*)&smB[2 * BPLANE + j0];
                    uint32_t b2h = *(const uint32_t*)&smB[2 * BPLANE + j0 + 8];

                    float d0[4] = {0.f, 0.f, 0.f, 0.f};
                    mma16(d0, a0, b0l, b0h);
                    #pragma unroll
                    for (int e = 0; e < 4; e++) accR[mt][nt][e] += d0[e];

                    mma16(accC[mt][nt], a0, b1l, b1h);
                    mma16(accC[mt][nt], a1, b0l, b0h);
                    mma16(accC[mt][nt], a1, b1l, b1h);
                    mma16(accC[mt][nt], a0, b2l, b2h);
                    mma16(accC[mt][nt], a2, b0l, b0h);
                }
            }
        }
        __syncthreads();
    }

    // ---- epilogue
    #pragma unroll
    for (int mt = 0; mt < 4; mt++) {
        int r0 = bm + wm * 64 + mt * 16 + tg;
        #pragma unroll
        for (int nt = 0; nt < 2; nt++) {
            int col = bn + wn * 16 + nt * 8 + 2 * tq;
            float v00 = accR[mt][nt][0] + accC[mt][nt][0];
            float v01 = accR[mt][nt][1] + accC[mt][nt][1];
            float v10 = accR[mt][nt][2] + accC[mt][nt][2];
            float v11 = accR[mt][nt][3] + accC[mt][nt][3];
            if (EPI == 1 || EPI == 2) {
                float b0 = bias[col], b1 = bias[col + 1];
                v00 += b0; v01 += b1; v10 += b0; v11 += b1;
                if (EPI == 1) {
                    v00 = fmaxf(v00, 0.f); v01 = fmaxf(v01, 0.f);
                    v10 = fmaxf(v10, 0.f); v11 = fmaxf(v11, 0.f);
                }
            }
            if (EPI == 1) {
                __nv_bfloat16 p00[3], p01[3], p10[3], p11[3];
                split3(v00, p00[0], p00[1], p00[2]);
                split3(v01, p01[0], p01[1], p01[2]);
                split3(v10, p10[0], p10[1], p10[2]);
                split3(v11, p11[0], p11[1], p11[2]);
                #pragma unroll
                for (int p = 0; p < 3; p++) {
                    __nv_bfloat162 w0; w0.x = p00[p]; w0.y = p01[p];
                    __nv_bfloat162 w1; w1.x = p10[p]; w1.y = p11[p];
                    *(__nv_bfloat162*)&Cp[p * strCp + (size_t)r0 * ldc + col]       = w0;
                    *(__nv_bfloat162*)&Cp[p * strCp + (size_t)(r0 + 8) * ldc + col] = w1;
                }
            } else {
                *(float2*)(Cf + (size_t)r0 * ldc + col)       = make_float2(v00, v01);
                *(float2*)(Cf + (size_t)(r0 + 8) * ldc + col) = make_float2(v10, v11);
            }
        }
    }
}

// -------------------- residual + bias + LayerNorm (+ split3 planes out) -------
__global__ __launch_bounds__(128)
void ln_split(const float* __restrict__ gin, const float* __restrict__ bias,
              const float* __restrict__ res, const float* __restrict__ g,
              const float* __restrict__ bt, float* __restrict__ out,
              __nv_bfloat16* __restrict__ planes)
{
    const int row = blockIdx.x, t = threadIdx.x;
    float v = gin[(size_t)row * Hv + t] + bias[t] + res[(size_t)row * Hv + t];
    __shared__ float ws[4], ws2[4];
    int lane = t & 31, wid = t >> 5;
    float s = v, s2 = v * v;
    #pragma unroll
    for (int o = 16; o > 0; o >>= 1) {
        s  += __shfl_xor_sync(0xffffffffu, s,  o);
        s2 += __shfl_xor_sync(0xffffffffu, s2, o);
    }
    if (lane == 0) { ws[wid] = s; ws2[wid] = s2; }
    __syncthreads();
    float mu  = (ws[0] + ws[1] + ws[2] + ws[3]) * (1.f / Hv);
    float var = (ws2[0] + ws2[1] + ws2[2] + ws2[3]) * (1.f / Hv) - mu * mu;
    float r = (v - mu) * rsqrtf(var + 1e-5f) * g[t] + bt[t];
    size_t idx = (size_t)row * Hv + t;
    out[idx] = r;
    __nv_bfloat16 b0, b1, b2;
    split3(r, b0, b1, b2);
    planes[idx] = b0; planes[HS_STRIDE + idx] = b1; planes[2 * HS_STRIDE + idx] = b2;
}

// ============================================================================
// DECODER ENGINE: verbatim R3 fp32 f32x2 kernels (passed at 5.16e-8)
// ============================================================================
__device__ __forceinline__ unsigned long long bcast2(float x) {
    unsigned long long r;
    asm("mov.b64 %0, {%1, %1};" : "=l"(r) : "f"(x));
    return r;
}
__device__ __forceinline__ void fma2(unsigned long long& d,
                                     unsigned long long a, unsigned long long b) {
    asm("fma.rn.f32x2 %0, %1, %2, %0;" : "+l"(d) : "l"(a), "l"(b));
}
__device__ __forceinline__ float2 unpk2(unsigned long long v) {
    float lo, hi;
    asm("mov.b64 {%0, %1}, %2;" : "=f"(lo), "=f"(hi) : "l"(v));
    return make_float2(lo, hi);
}

template<int BM, int EPI>
__global__ __launch_bounds__(256, 2)
void sgemm_k(const float* __restrict__ A, const float* __restrict__ B,
             const float* __restrict__ bias, const float* __restrict__ res,
             const float* __restrict__ lng, const float* __restrict__ lnb,
             float* __restrict__ C, int M, int N, int K)
{
    constexpr int TM = BM / 16;
    constexpr int TP = TM / 2;
    constexpr int NA = (BM * 16) / 1024;
    __shared__ __align__(16) float As[2][16][BM];
    __shared__ __align__(16) float Bs[2][16][128];

    const int tid = threadIdx.x;
    const int tx = tid & 15, ty = tid >> 4;
    const int bm = blockIdx.y * BM;
    const int bn = blockIdx.x * 128;

    const float* Ab = A + (size_t)bm * K;
    const float* Bb = B + bn;

    float4 ra[NA], rb[2];
    #pragma unroll
    for (int i = 0; i < NA; i++) {
        int lin = tid + i * 256;
        int r = lin >> 2, c4 = (lin & 3) << 2;
        ra[i] = *(const float4*)(Ab + (size_t)r * K + c4);
    }
    #pragma unroll
    for (int i = 0; i < 2; i++) {
        int lin = tid + i * 256;
        int r = lin >> 5, c4 = (lin & 31) << 2;
        rb[i] = *(const float4*)(Bb + (size_t)r * N + c4);
    }
    #pragma unroll
    for (int i = 0; i < NA; i++) {
        int lin = tid + i * 256;
        int r = lin >> 2, c4 = (lin & 3) << 2;
        As[0][c4 + 0][r] = ra[i].x; As[0][c4 + 1][r] = ra[i].y;
        As[0][c4 + 2][r] = ra[i].z; As[0][c4 + 3][r] = ra[i].w;
    }
    #pragma unroll
    for (int i = 0; i < 2; i++) {
        int lin = tid + i * 256;
        int r = lin >> 5, c4 = (lin & 31) << 2;
        *(float4*)&Bs[0][r][c4] = rb[i];
    }
    __syncthreads();

    unsigned long long acc[TP][8];
    #pragma unroll
    for (int i = 0; i < TP; i++)
        #pragma unroll
        for (int j = 0; j < 8; j++) acc[i][j] = 0ull;

    int buf = 0;
    for (int k0 = 0; k0 < K; k0 += 16) {
        const bool has_next = (k0 + 16) < K;
        if (has_next) {
            #pragma unroll
            for (int i = 0; i < NA; i++) {
                int lin = tid + i * 256;
                int r = lin >> 2, c4 = (lin & 3) << 2;
                ra[i] = *(const float4*)(Ab + (size_t)r * K + k0 + 16 + c4);
            }
            #pragma unroll
            for (int i = 0; i < 2; i++) {
                int lin = tid + i * 256;
                int r = lin >> 5, c4 = (lin & 31) << 2;
                rb[i] = *(const float4*)(Bb + (size_t)(k0 + 16 + r) * N + c4);
            }
        }
        #pragma unroll
        for (int kk = 0; kk < 16; kk++) {
            unsigned long long a2[TP];
            #pragma unroll
            for (int i = 0; i < TP; i += 2) {
                ulonglong2 t = *(const ulonglong2*)&As[buf][kk][ty * TM + i * 2];
                a2[i] = t.x; a2[i + 1] = t.y;
            }
            float4 bf0 = *(const float4*)&Bs[buf][kk][tx * 8];
            float4 bf1 = *(const float4*)&Bs[buf][kk][tx * 8 + 4];
            unsigned long long bb[8];
            bb[0] = bcast2(bf0.x); bb[1] = bcast2(bf0.y);
            bb[2] = bcast2(bf0.z); bb[3] = bcast2(bf0.w);
            bb[4] = bcast2(bf1.x); bb[5] = bcast2(bf1.y);
            bb[6] = bcast2(bf1.z); bb[7] = bcast2(bf1.w);
            #pragma unroll
            for (int i = 0; i < TP; i++)
                #pragma unroll
                for (int j = 0; j < 8; j++) fma2(acc[i][j], a2[i], bb[j]);
        }
        if (has_next) {
            int nb = buf ^ 1;
            #pragma unroll
            for (int i = 0; i < NA; i++) {
                int lin = tid + i * 256;
                int r = lin >> 2, c4 = (lin & 3) << 2;
                As[nb][c4 + 0][r] = ra[i].x; As[nb][c4 + 1][r] = ra[i].y;
                As[nb][c4 + 2][r] = ra[i].z; As[nb][c4 + 3][r] = ra[i].w;
            }
            #pragma unroll
            for (int i = 0; i < 2; i++) {
                int lin = tid + i * 256;
                int r = lin >> 5, c4 = (lin & 31) << 2;
                *(float4*)&Bs[nb][r][c4] = rb[i];
            }
            __syncthreads();
            buf = nb;
        }
    }

    float bv[8] = {0.f,0.f,0.f,0.f,0.f,0.f,0.f,0.f};
    if (bias) {
        *(float4*)&bv[0] = *(const float4*)(bias + bn + tx * 8);
        *(float4*)&bv[4] = *(const float4*)(bias + bn + tx * 8 + 4);
    }
    #pragma unroll
    for (int ip = 0; ip < TP; ip++) {
        #pragma unroll
        for (int e = 0; e < 2; e++) {
            int row = bm + ty * TM + ip * 2 + e;
            float o[8];
            #pragma unroll
            for (int j = 0; j < 8; j++) {
                float2 p = unpk2(acc[ip][j]);
                float v = (e == 0 ? p.x : p.y) + bv[j];
                if (EPI == 1) v = fmaxf(v, 0.f);
                o[j] = v;
            }
            float* cp = C + (size_t)row * N + bn + tx * 8;
            *(float4*)cp       = *(float4*)&o[0];
            *(float4*)(cp + 4) = *(float4*)&o[4];
        }
    }
}

__global__ __launch_bounds__(256, 2)
void bgemm_nt128(const float* __restrict__ A, const float* __restrict__ Kb,
                 float* __restrict__ C, float scale)
{
    __shared__ __align__(16) float As[2][16][128];
    __shared__ __align__(16) float Bs[2][16][128];
    const int tid = threadIdx.x;
    const int tx = tid & 15, ty = tid >> 4;
    const int b = blockIdx.z;
    const int i0 = blockIdx.y * 128, j0 = blockIdx.x * 128;

    const float* Ab = A  + ((size_t)b * Nv + i0) * Hv;
    const float* Kp = Kb + ((size_t)b * Nv + j0) * Hv;

    float4 ra[2], rb[2];
    #pragma unroll
    for (int i = 0; i < 2; i++) {
        int lin = tid + i * 256;
        int r = lin >> 2, c4 = (lin & 3) << 2;
        ra[i] = *(const float4*)(Ab + (size_t)r * Hv + c4);
        rb[i] = *(const float4*)(Kp + (size_t)r * Hv + c4);
    }
    #pragma unroll
    for (int i = 0; i < 2; i++) {
        int lin = tid + i * 256;
        int r = lin >> 2, c4 = (lin & 3) << 2;
        As[0][c4+0][r] = ra[i].x; As[0][c4+1][r] = ra[i].y;
        As[0][c4+2][r] = ra[i].z; As[0][c4+3][r] = ra[i].w;
        Bs[0][c4+0][r] = rb[i].x; Bs[0][c4+1][r] = rb[i].y;
        Bs[0][c4+2][r] = rb[i].z; Bs[0][c4+3][r] = rb[i].w;
    }
    __syncthreads();

    unsigned long long acc[4][8];
    #pragma unroll
    for (int i = 0; i < 4; i++)
        #pragma unroll
        for (int j = 0; j < 8; j++) acc[i][j] = 0ull;

    int buf = 0;
    for (int k0 = 0; k0 < Hv; k0 += 16) {
        const bool has_next = (k0 + 16) < Hv;
        if (has_next) {
            #pragma unroll
            for (int i = 0; i < 2; i++) {
                int lin = tid + i * 256;
                int r = lin >> 2, c4 = (lin & 3) << 2;
                ra[i] = *(const float4*)(Ab + (size_t)r * Hv + k0 + 16 + c4);
                rb[i] = *(const float4*)(Kp + (size_t)r * Hv + k0 + 16 + c4);
            }
        }
        #pragma unroll
        for (int kk = 0; kk < 16; kk++) {
            unsigned long long a2[4];
            {
                ulonglong2 t0 = *(const ulonglong2*)&As[buf][kk][ty * 8];
                ulonglong2 t1 = *(const ulonglong2*)&As[buf][kk][ty * 8 + 4];
                a2[0] = t0.x; a2[1] = t0.y; a2[2] = t1.x; a2[3] = t1.y;
            }
            float4 bf0 = *(const float4*)&Bs[buf][kk][tx * 8];
            float4 bf1 = *(const float4*)&Bs[buf][kk][tx * 8 + 4];
            unsigned long long bb[8];
            bb[0] = bcast2(bf0.x); bb[1] = bcast2(bf0.y);
            bb[2] = bcast2(bf0.z); bb[3] = bcast2(bf0.w);
            bb[4] = bcast2(bf1.x); bb[5] = bcast2(bf1.y);
            bb[6] = bcast2(bf1.z); bb[7] = bcast2(bf1.w);
            #pragma unroll
            for (int i = 0; i < 4; i++)
                #pragma unroll
                for (int j = 0; j < 8; j++) fma2(acc[i][j], a2[i], bb[j]);
        }
        if (has_next) {
            int nb = buf ^ 1;
            #pragma unroll
            for (int i = 0; i < 2; i++) {
                int lin = tid + i * 256;
                int r = lin >> 2, c4 = (lin & 3) << 2;
                As[nb][c4+0][r] = ra[i].x; As[nb][c4+1][r] = ra[i].y;
                As[nb][c4+2][r] = ra[i].z; As[nb][c4+3][r] = ra[i].w;
                Bs[nb][c4+0][r] = rb[i].x; Bs[nb][c4+1][r] = rb[i].y;
                Bs[nb][c4+2][r] = rb[i].z; Bs[nb][c4+3][r] = rb[i].w;
            }
            __syncthreads();
            buf = nb;
        }
    }

    #pragma unroll
    for (int ip = 0; ip < 4; ip++) {
        #pragma unroll
        for (int e = 0; e < 2; e++) {
            float* cp = C + ((size_t)b * Nv + i0 + ty * 8 + ip * 2 + e) * Nv + j0 + tx * 8;
            float o[8];
            #pragma unroll
            for (int j = 0; j < 8; j++) {
                float2 p = unpk2(acc[ip][j]);
                o[j] = scale * (e == 0 ? p.x : p.y);
            }
            *(float4*)cp       = *(float4*)&o[0];
            *(float4*)(cp + 4) = *(float4*)&o[4];
        }
    }
}

// -------------------- fused MHA (writes split-3 planes) --------------------
__global__ __launch_bounds__(256)
void attn_kernel(const float* __restrict__ qkv, __nv_bfloat16* __restrict__ outp)
{
    int b = blockIdx.x / HEADSv, hd = blockIdx.x % HEADSv;
    __shared__ float Ks[Nv][DHv];
    __shared__ float Vs[Nv][DHv];
    int t = threadIdx.x;
    const float* base = qkv + (size_t)b * Nv * (3 * Hv);
    {
        const float* krow = base + (size_t)t * (3 * Hv) + Hv + hd * DHv;
        const float* vrow = base + (size_t)t * (3 * Hv) + 2 * Hv + hd * DHv;
        #pragma unroll
        for (int c = 0; c < 4; c++) {
            float4 kv4 = *(const float4*)(krow + c * 4);
            Ks[t][c * 4 + 0] = kv4.x; Ks[t][c * 4 + 1] = kv4.y;
            Ks[t][c * 4 + 2] = kv4.z; Ks[t][c * 4 + 3] = kv4.w;
            float4 vv4 = *(const float4*)(vrow + c * 4);
            Vs[t][c * 4 + 0] = vv4.x; Vs[t][c * 4 + 1] = vv4.y;
            Vs[t][c * 4 + 2] = vv4.z; Vs[t][c * 4 + 3] = vv4.w;
        }
    }
    __syncthreads();

    float q[DHv];
    {
        const float* qrow = base + (size_t)t * (3 * Hv) + hd * DHv;
        #pragma unroll
        for (int d = 0; d < DHv; d++) q[d] = qrow[d];
    }
    float m = -INFINITY, sum = 0.f, acc[DHv];
    #pragma unroll
    for (int d = 0; d < DHv; d++) acc[d] = 0.f;

    for (int j = 0; j < Nv; j++) {
        float s = 0.f;
        #pragma unroll
        for (int d = 0; d < DHv; d++) s += q[d] * Ks[j][d];
        s *= 0.25f;
        float mnew = fmaxf(m, s);
        float corr = expf(m - mnew);
        float p = expf(s - mnew);
        sum = sum * corr + p;
        #pragma unroll
        for (int d = 0; d < DHv; d++) acc[d] = acc[d] * corr + p * Vs[j][d];
        m = mnew;
    }
    float inv = 1.f / sum;
    size_t off = ((size_t)b * Nv + t) * Hv + hd * DHv;
    #pragma unroll
    for (int d = 0; d < DHv; d++) {
        __nv_bfloat16 b0, b1, b2;
        split3(acc[d] * inv, b0, b1, b2);
        outp[off + d] = b0;
        outp[HS_STRIDE + off + d] = b1;
        outp[2 * HS_STRIDE + off + d] = b2;
    }
}

// -------------------- small helpers --------------------
__global__ __launch_bounds__(128)
void graph_mean(const float* __restrict__ node, float* __restrict__ graph)
{
    int b = blockIdx.x, h = threadIdx.x;
    float s = 0.f;
    for (int n = 0; n < Nv; n++) s += node[((size_t)b * Nv + n) * Hv + h];
    graph[b * Hv + h] = s * (1.f / Nv);
}

__global__ __launch_bounds__(128)
void vecmat(const float* __restrict__ v, const float* __restrict__ W, float* __restrict__ out)
{
    int j = threadIdx.x;
    float s = 0.f;
    for (int i = 0; i < Hv; i++) s += v[i] * W[i * Hv + j];
    out[j] = s;
}

__global__ void add_gq(float* __restrict__ baseQ, const float* __restrict__ gq)
{
    int idx = blockIdx.x * blockDim.x + threadIdx.x;
    if (idx < Bv * Nv * Hv) {
        int b = idx / (Nv * Hv);
        int h = idx & (Hv - 1);
        baseQ[idx] += gq[b * Hv + h];
    }
}

// -------------------- greedy decode --------------------
__global__ __launch_bounds__(256)
void decode_kernel(const float* __restrict__ baseL, const float* __restrict__ cross,
                   float* __restrict__ out_tours, float* __restrict__ out_logp)
{
    int idx = blockIdx.x * blockDim.x + threadIdx.x;
    if (idx >= Bv * Nv) return;
    int b = idx >> 8, s = idx & 255;
    unsigned mask[8] = {0, 0, 0, 0, 0, 0, 0, 0};
    mask[s >> 5] |= 1u << (s & 31);
    const float* bl = baseL + ((size_t)b * Nv + s) * Nv;
    int cur = s;
    float logp = 0.f;
    out_tours[(size_t)idx * TOURLEN] = (float)s;
    for (int step = 1; step < TOURLEN; step++) {
        const float* cr = cross + ((size_t)b * Nv + cur) * Nv;
        float mx = -3.4e38f;
        int arg = 0;
        for (int n = 0; n < Nv; n++) {
            bool vis = (mask[n >> 5] >> (n & 31)) & 1u;
            float v = vis ? -1e9f : (__ldg(bl + n) + __ldg(cr + n));
            if (v > mx) { mx = v; arg = n; }
        }
        float sum = 0.f;
        for (int n = 0; n < Nv; n++) {
            bool vis = (mask[n >> 5] >> (n & 31)) & 1u;
            if (!vis) sum += expf(__ldg(bl + n) + __ldg(cr + n) - mx);
        }
        logp -= logf(sum);
        mask[arg >> 5] |= 1u << (arg & 31);
        cur = arg;
        out_tours[(size_t)idx * TOURLEN + step] = (float)arg;
    }
    out_logp[idx] = logp;
}

// -------------------- host orchestration --------------------
extern "C" void kernel_launch(void* const* d_in, const int* in_sizes, int n_in,
                              void* d_out, int out_size)
{
    const float* x      = (const float*)d_in[0];
    const float* init_W = (const float*)d_in[1];
    const float* init_b = (const float*)d_in[2];
    const float* Wqkv   = (const float*)d_in[3];
    const float* bqkv   = (const float*)d_in[4];
    const float* Wo     = (const float*)d_in[5];
    const float* bo     = (const float*)d_in[6];
    const float* W1     = (const float*)d_in[7];
    const float* b1     = (const float*)d_in[8];
    const float* W2     = (const float*)d_in[9];
    const float* b2     = (const float*)d_in[10];
    const float* ln1_g  = (const float*)d_in[11];
    const float* ln1_b  = (const float*)d_in[12];
    const float* ln2_g  = (const float*)d_in[13];
    const float* ln2_b  = (const float*)d_in[14];
    const float* Wquery = (const float*)d_in[15];
    const float* bquery = (const float*)d_in[16];
    const float* Wq     = (const float*)d_in[17];
    const float* Wk     = (const float*)d_in[18];

    float *h, *tmp, *kbuf, *Mbuf, *baseQ, *graph, *gq;
    float *W1q, *W2q, *W3q, *bq2, *baseL, *cross;
    __nv_bfloat16 *hs, *atts, *ffs, *wqkvt, *wot, *w1t, *w2t;
    cudaGetSymbolAddress((void**)&h,     g_h);
    cudaGetSymbolAddress((void**)&tmp,   g_tmp);
    cudaGetSymbolAddress((void**)&kbuf,  g_k);
    cudaGetSymbolAddress((void**)&Mbuf,  g_M);
    cudaGetSymbolAddress((void**)&baseQ, g_baseQ);
    cudaGetSymbolAddress((void**)&graph, g_graph);
    cudaGetSymbolAddress((void**)&gq,    g_gq);
    cudaGetSymbolAddress((void**)&W1q,   g_W1q);
    cudaGetSymbolAddress((void**)&W2q,   g_W2q);
    cudaGetSymbolAddress((void**)&W3q,   g_W3q);
    cudaGetSymbolAddress((void**)&bq2,   g_bq2);
    cudaGetSymbolAddress((void**)&baseL, g_baseL);
    cudaGetSymbolAddress((void**)&cross, g_cross);
    cudaGetSymbolAddress((void**)&hs,    g_hs);
    cudaGetSymbolAddress((void**)&atts,  g_atts);
    cudaGetSymbolAddress((void**)&ffs,   g_ffs);
    cudaGetSymbolAddress((void**)&wqkvt, g_wqkvt);
    cudaGetSymbolAddress((void**)&wot,   g_wot);
    cudaGetSymbolAddress((void**)&w1t,   g_w1t);
    cudaGetSymbolAddress((void**)&w2t,   g_w2t);

    const int MBm = MTOK / 128;   // 128 CTA rows

    // ---- weight prep (once per launch)
    for (int l = 0; l < Lv; l++) {
        wprep<<<(Hv * 3 * Hv + 255) / 256, 256>>>(
            Wqkv + (size_t)l * Hv * 3 * Hv, wqkvt + (size_t)l * 3 * (3 * Hv) * Hv, Hv, 3 * Hv);
        wprep<<<(Hv * Hv + 255) / 256, 256>>>(
            Wo + (size_t)l * Hv * Hv, wot + (size_t)l * 3 * Hv * Hv, Hv, Hv);
        wprep<<<(Hv * DFFv + 255) / 256, 256>>>(
            W1 + (size_t)l * Hv * DFFv, w1t + (size_t)l * 3 * DFFv * Hv, Hv, DFFv);
        wprep<<<(DFFv * Hv + 255) / 256, 256>>>(
            W2 + (size_t)l * DFFv * Hv, w2t + (size_t)l * 3 * Hv * DFFv, DFFv, Hv);
    }

    // ---- init embedding: h = x @ init_W + init_b  (K=16, fp32), then split
    sgemm_k<128, 0><<<dim3(1, MBm), 256>>>(
        x, init_W, init_b, nullptr, nullptr, nullptr, h, MTOK, Hv, Din);
    split_act<<<(MTOK * Hv + 255) / 256, 256>>>(h, hs, (size_t)MTOK * Hv, HS_STRIDE);

    // ---- encoder layers (HMMA bf16x6 on pre-split planes)
    const size_t WQKV_PS = (size_t)(3 * Hv) * Hv;   // 49152
    const size_t WO_PS   = (size_t)Hv * Hv;         // 16384
    const size_t W1_PS   = (size_t)DFFv * Hv;       // 262144
    const size_t W2_PS   = (size_t)Hv * DFFv;       // 262144
    for (int l = 0; l < Lv; l++) {
        // qkv = h @ Wqkv + bqkv  (f32 out)
        mma_gemm<2><<<dim3(6, MBm), 256, SMB_BYTES>>>(
            hs, HS_STRIDE, wqkvt + (size_t)l * 3 * WQKV_PS, WQKV_PS,
            bqkv + (size_t)l * 3 * Hv, tmp, nullptr, 0, Hv, 3 * Hv);
        attn_kernel<<<Bv * HEADSv, 256>>>(tmp, atts);
        // tmp = att @ Wo (f32), then h = LN(h + tmp + bo) and h-planes
        mma_gemm<0><<<dim3(2, MBm), 256, SMB_BYTES>>>(
            atts, HS_STRIDE, wot + (size_t)l * 3 * WO_PS, WO_PS,
            nullptr, tmp, nullptr, 0, Hv, Hv);
        ln_split<<<MTOK, 128>>>(tmp, bo + (size_t)l * Hv, h,
                                ln1_g + (size_t)l * Hv, ln1_b + (size_t)l * Hv, h, hs);
        // ff-planes = split3(relu(h @ W1 + b1))
        mma_gemm<1><<<dim3(DFFv / 64, MBm), 256, SMB_BYTES>>>(
            hs, HS_STRIDE, w1t + (size_t)l * 3 * W1_PS, W1_PS,
            b1 + (size_t)l * DFFv, nullptr, ffs, FF_STRIDE, Hv, DFFv);
        // tmp = ff @ W2 (f32), then h = LN(h + tmp + b2) and h-planes
        mma_gemm<0><<<dim3(2, MBm), 256, SMB_BYTES>>>(
            ffs, FF_STRIDE, w2t + (size_t)l * 3 * W2_PS, W2_PS,
            nullptr, tmp, nullptr, 0, DFFv, Hv);
        ln_split<<<MTOK, 128>>>(tmp, b2 + (size_t)l * Hv, h,
                                ln2_g + (size_t)l * Hv, ln2_b + (size_t)l * Hv, h, hs);
    }

    // ---- decoder precompute: EXACT R3 fp32 path
    graph_mean<<<Bv, 128>>>(h, graph);
    sgemm_k<128, 0><<<dim3(1, MBm), 256>>>(
        h, Wk, nullptr, nullptr, nullptr, nullptr, kbuf, MTOK, Hv, Hv);

    sgemm_k<64, 0><<<dim3(1, 2), 256>>>(Wquery,               Wq, nullptr, nullptr, nullptr, nullptr, W1q, Hv, Hv, Hv);
    sgemm_k<64, 0><<<dim3(1, 2), 256>>>(Wquery + Hv * Hv,     Wq, nullptr, nullptr, nullptr, nullptr, W2q, Hv, Hv, Hv);
    sgemm_k<64, 0><<<dim3(1, 2), 256>>>(Wquery + 2 * Hv * Hv, Wq, nullptr, nullptr, nullptr, nullptr, W3q, Hv, Hv, Hv);
    vecmat<<<1, 128>>>(bquery, Wq, bq2);

    sgemm_k<64, 0><<<dim3(1, 1), 256>>>(graph, W1q, bq2, nullptr, nullptr, nullptr, gq, Bv, Hv, Hv);
    sgemm_k<128, 0><<<dim3(1, MBm), 256>>>(
        h, W2q, nullptr, nullptr, nullptr, nullptr, baseQ, MTOK, Hv, Hv);
    add_gq<<<(Bv * Nv * Hv + 255) / 256, 256>>>(baseQ, gq);
    sgemm_k<128, 0><<<dim3(1, MBm), 256>>>(
        h, W3q, nullptr, nullptr, nullptr, nullptr, Mbuf, MTOK, Hv, Hv);

    bgemm_nt128<<<dim3(2, 2, Bv), 256>>>(baseQ, kbuf, baseL, LSCALE);
    bgemm_nt128<<<dim3(2, 2, Bv), 256>>>(Mbuf,  kbuf, cross, LSCALE);

    // ---- greedy decode
    float* out = (float*)d_out;
    decode_kernel<<<(Bv * Nv + 255) / 256, 256>>>(baseL, cross, out, out + (size_t)Bv * Nv * TOURLEN);
}

// round 11
// speedup vs baseline: 1.0116x; 1.0116x over previous
#include <cuda_runtime.h>
#include <cuda_bf16.h>
#include <math.h>
#include <stdint.h>

#define Bv   64
#define Nv   256
#define Din  16
#define Hv   128
#define Lv   6
#define DFFv 2048
#define HEADSv 8
#define DHv  16
#define TOURLEN 16
#define LSCALE 0.08838834764831845f   /* H^-0.5 */

#define MTOK (Bv*Nv)                  /* 16384 */
#define HS_STRIDE ((size_t)MTOK*Hv)
#define FF_STRIDE ((size_t)MTOK*DFFv)

// -------------------- device scratch --------------------
__device__ float g_h[MTOK*Hv];
__device__ float g_tmp[MTOK*3*Hv];
__device__ float g_k[MTOK*Hv];
__device__ float g_M[MTOK*Hv];
__device__ float g_baseQ[MTOK*Hv];
__device__ float g_graph[Bv*Hv];
__device__ float g_gq[Bv*Hv];
__device__ float g_W1q[Hv*Hv];
__device__ float g_W2q[Hv*Hv];
__device__ float g_W3q[Hv*Hv];
__device__ float g_bq2[Hv];
__device__ float g_baseL[Bv*Nv*Nv];
__device__ float g_cross[Bv*Nv*Nv];

__device__ __nv_bfloat16 g_hs[3*MTOK*Hv];
__device__ __nv_bfloat16 g_atts[3*MTOK*Hv];
__device__ __nv_bfloat16 g_ffs[(size_t)3*MTOK*DFFv];
__device__ __nv_bfloat16 g_wqkvt[(size_t)Lv*3*(3*Hv)*Hv];
__device__ __nv_bfloat16 g_wot[(size_t)Lv*3*Hv*Hv];
__device__ __nv_bfloat16 g_w1t[(size_t)Lv*3*DFFv*Hv];
__device__ __nv_bfloat16 g_w2t[(size_t)Lv*3*Hv*DFFv];

// -------------------- split3 --------------------
__device__ __forceinline__ void split3(float v, __nv_bfloat16& b0,
                                       __nv_bfloat16& b1, __nv_bfloat16& b2) {
    b0 = __float2bfloat16(v);
    float r = v - __bfloat162float(b0);
    b1 = __float2bfloat16(r);
    float r2 = r - __bfloat162float(b1);
    b2 = __float2bfloat16(r2);
}
__device__ __forceinline__ void mma16(float* d, const uint32_t* a, uint32_t b0, uint32_t b1) {
    asm volatile(
        "mma.sync.aligned.m16n8k16.row.col.f32.bf16.bf16.f32 "
        "{%0,%1,%2,%3}, {%4,%5,%6,%7}, {%8,%9}, {%0,%1,%2,%3};"
        : "+f"(d[0]), "+f"(d[1]), "+f"(d[2]), "+f"(d[3])
        : "r"(a[0]), "r"(a[1]), "r"(a[2]), "r"(a[3]), "r"(b0), "r"(b1));
}

// -------------------- weight prep (all layers in one launch) --------------------
__global__ __launch_bounds__(256)
void wprep_all(const float* __restrict__ W, __nv_bfloat16* __restrict__ out,
               int K, int N, size_t wlstride, size_t olstride)
{
    int l = blockIdx.y;
    const float* Wl = W + (size_t)l * wlstride;
    __nv_bfloat16* ol = out + (size_t)l * olstride;
    int idx = blockIdx.x * 256 + threadIdx.x;
    if (idx >= K * N) return;
    int n = idx / K, k = idx - n * K;
    float v = Wl[(size_t)k * N + n];
    __nv_bfloat16 b0, b1, b2;
    split3(v, b0, b1, b2);
    size_t ps = (size_t)N * K;
    ol[idx] = b0; ol[ps + idx] = b1; ol[2 * ps + idx] = b2;
}

// -------------------- split activation -> planes --------------------
__global__ __launch_bounds__(256)
void split_act(const float* __restrict__ in, __nv_bfloat16* __restrict__ out, size_t n, size_t ps)
{
    size_t idx = (size_t)blockIdx.x * 256 + threadIdx.x;
    if (idx >= n) return;
    __nv_bfloat16 b0, b1, b2;
    split3(in[idx], b0, b1, b2);
    out[idx] = b0; out[ps + idx] = b1; out[2 * ps + idx] = b2;
}

// ============================================================================
// mma_gemm: C[128x64 tile] = A @ B^T over pre-split bf16 planes.
// Product sequence per accumulator identical to R10 (bitwise-same result);
// corrections interleaved across nt to break the dependent-MMA chain.
// EPI: 0 -> f32 out, 2 -> bias + f32 out, 1 -> bias+relu+split3 -> planes.
// ============================================================================
#define APLANE 5120
#define BPLANE 2560
#define SMB_BYTES ((3*APLANE + 3*BPLANE) * 2)

template<int EPI>
__global__ __launch_bounds__(256, 2)
void mma_gemm(const __nv_bfloat16* __restrict__ A, size_t strA,
              const __nv_bfloat16* __restrict__ B, size_t strB,
              const float* __restrict__ bias,
              float* __restrict__ Cf, __nv_bfloat16* __restrict__ Cp, size_t strCp,
              int K, int ldc)
{
    extern __shared__ __nv_bfloat16 smh[];
    __nv_bfloat16* smA = smh;
    __nv_bfloat16* smB = smh + 3 * APLANE;

    const int tid = threadIdx.x;
    const int lane = tid & 31;
    const int wid = tid >> 5;
    const int wm = wid & 1;
    const int wn = wid >> 1;
    const int tg = lane >> 2;
    const int tq = lane & 3;
    const int bm = blockIdx.y * 128, bn = blockIdx.x * 64;

    float accR[4][2][4];
    float accC[4][2][4];
    #pragma unroll
    for (int i = 0; i < 4; i++)
        #pragma unroll
        for (int j = 0; j < 2; j++)
            #pragma unroll
            for (int e = 0; e < 4; e++) { accR[i][j][e] = 0.f; accC[i][j][e] = 0.f; }

    for (int kc = 0; kc < K; kc += 32) {
        #pragma unroll
        for (int it = 0; it < 6; it++) {
            int lin = tid + it * 256;
            int p = lin >> 9, rem = lin & 511;
            int r = rem >> 2, kq = (rem & 3) << 3;
            *(uint4*)&smA[p * APLANE + r * 40 + kq] =
                *(const uint4*)&A[p * strA + (size_t)(bm + r) * K + kc + kq];
        }
        #pragma unroll
        for (int it = 0; it < 3; it++) {
            int lin = tid + it * 256;
            int p = lin >> 8, rem = lin & 255;
            int n = rem >> 2, kq = (rem & 3) << 3;
            *(uint4*)&smB[p * BPLANE + n * 40 + kq] =
                *(const uint4*)&B[p * strB + (size_t)(bn + n) * K + kc + kq];
        }
        __syncthreads();

        #pragma unroll
        for (int ks = 0; ks < 32; ks += 16) {
            #pragma unroll
            for (int mt = 0; mt < 4; mt++) {
                const int r = wm * 64 + mt * 16 + tg;
                uint32_t a0[4], a1[4], a2[4];
                {
                    const int i00 = r * 40 + ks + 2 * tq;
                    const int i10 = (r + 8) * 40 + ks + 2 * tq;
                    a0[0] = *(const uint32_t*)&smA[i00];
                    a0[1] = *(const uint32_t*)&smA[i10];
                    a0[2] = *(const uint32_t*)&smA[i00 + 8];
                    a0[3] = *(const uint32_t*)&smA[i10 + 8];
                    a1[0] = *(const uint32_t*)&smA[APLANE + i00];
                    a1[1] = *(const uint32_t*)&smA[APLANE + i10];
                    a1[2] = *(const uint32_t*)&smA[APLANE + i00 + 8];
                    a1[3] = *(const uint32_t*)&smA[APLANE + i10 + 8];
                    a2[0] = *(const uint32_t*)&smA[2 * APLANE + i00];
                    a2[1] = *(const uint32_t*)&smA[2 * APLANE + i10];
                    a2[2] = *(const uint32_t*)&smA[2 * APLANE + i00 + 8];
                    a2[3] = *(const uint32_t*)&smA[2 * APLANE + i10 + 8];
                }
                // load B fragments for both nt up front
                uint32_t bf[2][6];
                #pragma unroll
                for (int nt = 0; nt < 2; nt++) {
                    const int n = wn * 16 + nt * 8 + tg;
                    const int j0 = n * 40 + ks + 2 * tq;
                    bf[nt][0] = *(const uint32_t*)&smB[j0];
                    bf[nt][1] = *(const uint32_t*)&smB[j0 + 8];
                    bf[nt][2] = *(const uint32_t*)&smB[BPLANE + j0];
                    bf[nt][3] = *(const uint32_t*)&smB[BPLANE + j0 + 8];
                    bf[nt][4] = *(const uint32_t*)&smB[2 * BPLANE + j0];
                    bf[nt][5] = *(const uint32_t*)&smB[2 * BPLANE + j0 + 8];
                }
                // main terms: zero-init mma, unbiased FADD into accR (independent)
                #pragma unroll
                for (int nt = 0; nt < 2; nt++) {
                    float d0[4] = {0.f, 0.f, 0.f, 0.f};
                    mma16(d0, a0, bf[nt][0], bf[nt][1]);
                    #pragma unroll
                    for (int e = 0; e < 4; e++) accR[mt][nt][e] += d0[e];
                }
                // corrections interleaved across nt (same per-acc sequence as R10)
                mma16(accC[mt][0], a0, bf[0][2], bf[0][3]);
                mma16(accC[mt][1], a0, bf[1][2], bf[1][3]);
                mma16(accC[mt][0], a1, bf[0][0], bf[0][1]);
                mma16(accC[mt][1], a1, bf[1][0], bf[1][1]);
                mma16(accC[mt][0], a1, bf[0][2], bf[0][3]);
                mma16(accC[mt][1], a1, bf[1][2], bf[1][3]);
                mma16(accC[mt][0], a0, bf[0][4], bf[0][5]);
                mma16(accC[mt][1], a0, bf[1][4], bf[1][5]);
                mma16(accC[mt][0], a2, bf[0][0], bf[0][1]);
                mma16(accC[mt][1], a2, bf[1][0], bf[1][1]);
            }
        }
        __syncthreads();
    }

    #pragma unroll
    for (int mt = 0; mt < 4; mt++) {
        int r0 = bm + wm * 64 + mt * 16 + tg;
        #pragma unroll
        for (int nt = 0; nt < 2; nt++) {
            int col = bn + wn * 16 + nt * 8 + 2 * tq;
            float v00 = accR[mt][nt][0] + accC[mt][nt][0];
            float v01 = accR[mt][nt][1] + accC[mt][nt][1];
            float v10 = accR[mt][nt][2] + accC[mt][nt][2];
            float v11 = accR[mt][nt][3] + accC[mt][nt][3];
            if (EPI == 1 || EPI == 2) {
                float b0 = bias[col], b1 = bias[col + 1];
                v00 += b0; v01 += b1; v10 += b0; v11 += b1;
                if (EPI == 1) {
                    v00 = fmaxf(v00, 0.f); v01 = fmaxf(v01, 0.f);
                    v10 = fmaxf(v10, 0.f); v11 = fmaxf(v11, 0.f);
                }
            }
            if (EPI == 1) {
                __nv_bfloat16 p00[3], p01[3], p10[3], p11[3];
                split3(v00, p00[0], p00[1], p00[2]);
                split3(v01, p01[0], p01[1], p01[2]);
                split3(v10, p10[0], p10[1], p10[2]);
                split3(v11, p11[0], p11[1], p11[2]);
                #pragma unroll
                for (int p = 0; p < 3; p++) {
                    __nv_bfloat162 w0; w0.x = p00[p]; w0.y = p01[p];
                    __nv_bfloat162 w1; w1.x = p10[p]; w1.y = p11[p];
                    *(__nv_bfloat162*)&Cp[p * strCp + (size_t)r0 * ldc + col]       = w0;
                    *(__nv_bfloat162*)&Cp[p * strCp + (size_t)(r0 + 8) * ldc + col] = w1;
                }
            } else {
                *(float2*)(Cf + (size_t)r0 * ldc + col)       = make_float2(v00, v01);
                *(float2*)(Cf + (size_t)(r0 + 8) * ldc + col) = make_float2(v10, v11);
            }
        }
    }
}

// -------------------- residual + bias + LayerNorm (+ planes) -------
__global__ __launch_bounds__(128)
void ln_split(const float* __restrict__ gin, const float* __restrict__ bias,
              const float* __restrict__ res, const float* __restrict__ g,
              const float* __restrict__ bt, float* __restrict__ out,
              __nv_bfloat16* __restrict__ planes)
{
    const int row = blockIdx.x, t = threadIdx.x;
    float v = gin[(size_t)row * Hv + t] + bias[t] + res[(size_t)row * Hv + t];
    __shared__ float ws[4], ws2[4];
    int lane = t & 31, wid = t >> 5;
    float s = v, s2 = v * v;
    #pragma unroll
    for (int o = 16; o > 0; o >>= 1) {
        s  += __shfl_xor_sync(0xffffffffu, s,  o);
        s2 += __shfl_xor_sync(0xffffffffu, s2, o);
    }
    if (lane == 0) { ws[wid] = s; ws2[wid] = s2; }
    __syncthreads();
    float mu  = (ws[0] + ws[1] + ws[2] + ws[3]) * (1.f / Hv);
    float var = (ws2[0] + ws2[1] + ws2[2] + ws2[3]) * (1.f / Hv) - mu * mu;
    float r = (v - mu) * rsqrtf(var + 1e-5f) * g[t] + bt[t];
    size_t idx = (size_t)row * Hv + t;
    out[idx] = r;
    __nv_bfloat16 b0, b1, b2;
    split3(r, b0, b1, b2);
    planes[idx] = b0; planes[HS_STRIDE + idx] = b1; planes[2 * HS_STRIDE + idx] = b2;
}

// ============================================================================
// DECODER ENGINE: verbatim R3 fp32 f32x2 kernels
// ============================================================================
__device__ __forceinline__ unsigned long long bcast2(float x) {
    unsigned long long r;
    asm("mov.b64 %0, {%1, %1};" : "=l"(r) : "f"(x));
    return r;
}
__device__ __forceinline__ void fma2(unsigned long long& d,
                                     unsigned long long a, unsigned long long b) {
    asm("fma.rn.f32x2 %0, %1, %2, %0;" : "+l"(d) : "l"(a), "l"(b));
}
__device__ __forceinline__ float2 unpk2(unsigned long long v) {
    float lo, hi;
    asm("mov.b64 {%0, %1}, %2;" : "=f"(lo), "=f"(hi) : "l"(v));
    return make_float2(lo, hi);
}

template<int BM, int EPI>
__global__ __launch_bounds__(256, 2)
void sgemm_k(const float* __restrict__ A, const float* __restrict__ B,
             const float* __restrict__ bias, const float* __restrict__ res,
             const float* __restrict__ lng, const float* __restrict__ lnb,
             float* __restrict__ C, int M, int N, int K)
{
    constexpr int TM = BM / 16;
    constexpr int TP = TM / 2;
    constexpr int NA = (BM * 16) / 1024;
    __shared__ __align__(16) float As[2][16][BM];
    __shared__ __align__(16) float Bs[2][16][128];

    const int tid = threadIdx.x;
    const int tx = tid & 15, ty = tid >> 4;
    const int bm = blockIdx.y * BM;
    const int bn = blockIdx.x * 128;

    const float* Ab = A + (size_t)bm * K;
    const float* Bb = B + bn;

    float4 ra[NA], rb[2];
    #pragma unroll
    for (int i = 0; i < NA; i++) {
        int lin = tid + i * 256;
        int r = lin >> 2, c4 = (lin & 3) << 2;
        ra[i] = *(const float4*)(Ab + (size_t)r * K + c4);
    }
    #pragma unroll
    for (int i = 0; i < 2; i++) {
        int lin = tid + i * 256;
        int r = lin >> 5, c4 = (lin & 31) << 2;
        rb[i] = *(const float4*)(Bb + (size_t)r * N + c4);
    }
    #pragma unroll
    for (int i = 0; i < NA; i++) {
        int lin = tid + i * 256;
        int r = lin >> 2, c4 = (lin & 3) << 2;
        As[0][c4 + 0][r] = ra[i].x; As[0][c4 + 1][r] = ra[i].y;
        As[0][c4 + 2][r] = ra[i].z; As[0][c4 + 3][r] = ra[i].w;
    }
    #pragma unroll
    for (int i = 0; i < 2; i++) {
        int lin = tid + i * 256;
        int r = lin >> 5, c4 = (lin & 31) << 2;
        *(float4*)&Bs[0][r][c4] = rb[i];
    }
    __syncthreads();

    unsigned long long acc[TP][8];
    #pragma unroll
    for (int i = 0; i < TP; i++)
        #pragma unroll
        for (int j = 0; j < 8; j++) acc[i][j] = 0ull;

    int buf = 0;
    for (int k0 = 0; k0 < K; k0 += 16) {
        const bool has_next = (k0 + 16) < K;
        if (has_next) {
            #pragma unroll
            for (int i = 0; i < NA; i++) {
                int lin = tid + i * 256;
                int r = lin >> 2, c4 = (lin & 3) << 2;
                ra[i] = *(const float4*)(Ab + (size_t)r * K + k0 + 16 + c4);
            }
            #pragma unroll
            for (int i = 0; i < 2; i++) {
                int lin = tid + i * 256;
                int r = lin >> 5, c4 = (lin & 31) << 2;
                rb[i] = *(const float4*)(Bb + (size_t)(k0 + 16 + r) * N + c4);
            }
        }
        #pragma unroll
        for (int kk = 0; kk < 16; kk++) {
            unsigned long long a2[TP];
            #pragma unroll
            for (int i = 0; i < TP; i += 2) {
                ulonglong2 t = *(const ulonglong2*)&As[buf][kk][ty * TM + i * 2];
                a2[i] = t.x; a2[i + 1] = t.y;
            }
            float4 bf0 = *(const float4*)&Bs[buf][kk][tx * 8];
            float4 bf1 = *(const float4*)&Bs[buf][kk][tx * 8 + 4];
            unsigned long long bb[8];
            bb[0] = bcast2(bf0.x); bb[1] = bcast2(bf0.y);
            bb[2] = bcast2(bf0.z); bb[3] = bcast2(bf0.w);
            bb[4] = bcast2(bf1.x); bb[5] = bcast2(bf1.y);
            bb[6] = bcast2(bf1.z); bb[7] = bcast2(bf1.w);
            #pragma unroll
            for (int i = 0; i < TP; i++)
                #pragma unroll
                for (int j = 0; j < 8; j++) fma2(acc[i][j], a2[i], bb[j]);
        }
        if (has_next) {
            int nb = buf ^ 1;
            #pragma unroll
            for (int i = 0; i < NA; i++) {
                int lin = tid + i * 256;
                int r = lin >> 2, c4 = (lin & 3) << 2;
                As[nb][c4 + 0][r] = ra[i].x; As[nb][c4 + 1][r] = ra[i].y;
                As[nb][c4 + 2][r] = ra[i].z; As[nb][c4 + 3][r] = ra[i].w;
            }
            #pragma unroll
            for (int i = 0; i < 2; i++) {
                int lin = tid + i * 256;
                int r = lin >> 5, c4 = (lin & 31) << 2;
                *(float4*)&Bs[nb][r][c4] = rb[i];
            }
            __syncthreads();
            buf = nb;
        }
    }

    float bv[8] = {0.f,0.f,0.f,0.f,0.f,0.f,0.f,0.f};
    if (bias) {
        *(float4*)&bv[0] = *(const float4*)(bias + bn + tx * 8);
        *(float4*)&bv[4] = *(const float4*)(bias + bn + tx * 8 + 4);
    }
    #pragma unroll
    for (int ip = 0; ip < TP; ip++) {
        #pragma unroll
        for (int e = 0; e < 2; e++) {
            int row = bm + ty * TM + ip * 2 + e;
            float o[8];
            #pragma unroll
            for (int j = 0; j < 8; j++) {
                float2 p = unpk2(acc[ip][j]);
                float v = (e == 0 ? p.x : p.y) + bv[j];
                if (EPI == 1) v = fmaxf(v, 0.f);
                o[j] = v;
            }
            float* cp = C + (size_t)row * N + bn + tx * 8;
            *(float4*)cp       = *(float4*)&o[0];
            *(float4*)(cp + 4) = *(float4*)&o[4];
        }
    }
}

__global__ __launch_bounds__(256, 2)
void bgemm_nt128(const float* __restrict__ A, const float* __restrict__ Kb,
                 float* __restrict__ C, float scale)
{
    __shared__ __align__(16) float As[2][16][128];
    __shared__ __align__(16) float Bs[2][16][128];
    const int tid = threadIdx.x;
    const int tx = tid & 15, ty = tid >> 4;
    const int b = blockIdx.z;
    const int i0 = blockIdx.y * 128, j0 = blockIdx.x * 128;

    const float* Ab = A  + ((size_t)b * Nv + i0) * Hv;
    const float* Kp = Kb + ((size_t)b * Nv + j0) * Hv;

    float4 ra[2], rb[2];
    #pragma unroll
    for (int i = 0; i < 2; i++) {
        int lin = tid + i * 256;
        int r = lin >> 2, c4 = (lin & 3) << 2;
        ra[i] = *(const float4*)(Ab + (size_t)r * Hv + c4);
        rb[i] = *(const float4*)(Kp + (size_t)r * Hv + c4);
    }
    #pragma unroll
    for (int i = 0; i < 2; i++) {
        int lin = tid + i * 256;
        int r = lin >> 2, c4 = (lin & 3) << 2;
        As[0][c4+0][r] = ra[i].x; As[0][c4+1][r] = ra[i].y;
        As[0][c4+2][r] = ra[i].z; As[0][c4+3][r] = ra[i].w;
        Bs[0][c4+0][r] = rb[i].x; Bs[0][c4+1][r] = rb[i].y;
        Bs[0][c4+2][r] = rb[i].z; Bs[0][c4+3][r] = rb[i].w;
    }
    __syncthreads();

    unsigned long long acc[4][8];
    #pragma unroll
    for (int i = 0; i < 4; i++)
        #pragma unroll
        for (int j = 0; j < 8; j++) acc[i][j] = 0ull;

    int buf = 0;
    for (int k0 = 0; k0 < Hv; k0 += 16) {
        const bool has_next = (k0 + 16) < Hv;
        if (has_next) {
            #pragma unroll
            for (int i = 0; i < 2; i++) {
                int lin = tid + i * 256;
                int r = lin >> 2, c4 = (lin & 3) << 2;
                ra[i] = *(const float4*)(Ab + (size_t)r * Hv + k0 + 16 + c4);
                rb[i] = *(const float4*)(Kp + (size_t)r * Hv + k0 + 16 + c4);
            }
        }
        #pragma unroll
        for (int kk = 0; kk < 16; kk++) {
            unsigned long long a2[4];
            {
                ulonglong2 t0 = *(const ulonglong2*)&As[buf][kk][ty * 8];
                ulonglong2 t1 = *(const ulonglong2*)&As[buf][kk][ty * 8 + 4];
                a2[0] = t0.x; a2[1] = t0.y; a2[2] = t1.x; a2[3] = t1.y;
            }
            float4 bf0 = *(const float4*)&Bs[buf][kk][tx * 8];
            float4 bf1 = *(const float4*)&Bs[buf][kk][tx * 8 + 4];
            unsigned long long bb[8];
            bb[0] = bcast2(bf0.x); bb[1] = bcast2(bf0.y);
            bb[2] = bcast2(bf0.z); bb[3] = bcast2(bf0.w);
            bb[4] = bcast2(bf1.x); bb[5] = bcast2(bf1.y);
            bb[6] = bcast2(bf1.z); bb[7] = bcast2(bf1.w);
            #pragma unroll
            for (int i = 0; i < 4; i++)
                #pragma unroll
                for (int j = 0; j < 8; j++) fma2(acc[i][j], a2[i], bb[j]);
        }
        if (has_next) {
            int nb = buf ^ 1;
            #pragma unroll
            for (int i = 0; i < 2; i++) {
                int lin = tid + i * 256;
                int r = lin >> 2, c4 = (lin & 3) << 2;
                As[nb][c4+0][r] = ra[i].x; As[nb][c4+1][r] = ra[i].y;
                As[nb][c4+2][r] = ra[i].z; As[nb][c4+3][r] = ra[i].w;
                Bs[nb][c4+0][r] = rb[i].x; Bs[nb][c4+1][r] = rb[i].y;
                Bs[nb][c4+2][r] = rb[i].z; Bs[nb][c4+3][r] = rb[i].w;
            }
            __syncthreads();
            buf = nb;
        }
    }

    #pragma unroll
    for (int ip = 0; ip < 4; ip++) {
        #pragma unroll
        for (int e = 0; e < 2; e++) {
            float* cp = C + ((size_t)b * Nv + i0 + ty * 8 + ip * 2 + e) * Nv + j0 + tx * 8;
            float o[8];
            #pragma unroll
            for (int j = 0; j < 8; j++) {
                float2 p = unpk2(acc[ip][j]);
                o[j] = scale * (e == 0 ? p.x : p.y);
            }
            *(float4*)cp       = *(float4*)&o[0];
            *(float4*)(cp + 4) = *(float4*)&o[4];
        }
    }
}

// -------------------- fused MHA (writes split-3 planes) --------------------
__global__ __launch_bounds__(256)
void attn_kernel(const float* __restrict__ qkv, __nv_bfloat16* __restrict__ outp)
{
    int b = blockIdx.x / HEADSv, hd = blockIdx.x % HEADSv;
    __shared__ float Ks[Nv][DHv];
    __shared__ float Vs[Nv][DHv];
    int t = threadIdx.x;
    const float* base = qkv + (size_t)b * Nv * (3 * Hv);
    {
        const float* krow = base + (size_t)t * (3 * Hv) + Hv + hd * DHv;
        const float* vrow = base + (size_t)t * (3 * Hv) + 2 * Hv + hd * DHv;
        #pragma unroll
        for (int c = 0; c < 4; c++) {
            float4 kv4 = *(const float4*)(krow + c * 4);
            Ks[t][c * 4 + 0] = kv4.x; Ks[t][c * 4 + 1] = kv4.y;
            Ks[t][c * 4 + 2] = kv4.z; Ks[t][c * 4 + 3] = kv4.w;
            float4 vv4 = *(const float4*)(vrow + c * 4);
            Vs[t][c * 4 + 0] = vv4.x; Vs[t][c * 4 + 1] = vv4.y;
            Vs[t][c * 4 + 2] = vv4.z; Vs[t][c * 4 + 3] = vv4.w;
        }
    }
    __syncthreads();

    float q[DHv];
    {
        const float* qrow = base + (size_t)t * (3 * Hv) + hd * DHv;
        #pragma unroll
        for (int d = 0; d < DHv; d++) q[d] = qrow[d];
    }
    float m = -INFINITY, sum = 0.f, acc[DHv];
    #pragma unroll
    for (int d = 0; d < DHv; d++) acc[d] = 0.f;

    for (int j = 0; j < Nv; j++) {
        float s = 0.f;
        #pragma unroll
        for (int d = 0; d < DHv; d++) s += q[d] * Ks[j][d];
        s *= 0.25f;
        float mnew = fmaxf(m, s);
        float corr = expf(m - mnew);
        float p = expf(s - mnew);
        sum = sum * corr + p;
        #pragma unroll
        for (int d = 0; d < DHv; d++) acc[d] = acc[d] * corr + p * Vs[j][d];
        m = mnew;
    }
    float inv = 1.f / sum;
    size_t off = ((size_t)b * Nv + t) * Hv + hd * DHv;
    #pragma unroll
    for (int d = 0; d < DHv; d++) {
        __nv_bfloat16 b0, b1, b2;
        split3(acc[d] * inv, b0, b1, b2);
        outp[off + d] = b0;
        outp[HS_STRIDE + off + d] = b1;
        outp[2 * HS_STRIDE + off + d] = b2;
    }
}

// -------------------- small helpers --------------------
__global__ __launch_bounds__(128)
void graph_mean(const float* __restrict__ node, float* __restrict__ graph)
{
    int b = blockIdx.x, h = threadIdx.x;
    float s = 0.f;
    for (int n = 0; n < Nv; n++) s += node[((size_t)b * Nv + n) * Hv + h];
    graph[b * Hv + h] = s * (1.f / Nv);
}

__global__ __launch_bounds__(128)
void vecmat(const float* __restrict__ v, const float* __restrict__ W, float* __restrict__ out)
{
    int j = threadIdx.x;
    float s = 0.f;
    for (int i = 0; i < Hv; i++) s += v[i] * W[i * Hv + j];
    out[j] = s;
}

__global__ void add_gq(float* __restrict__ baseQ, const float* __restrict__ gq)
{
    int idx = blockIdx.x * blockDim.x + threadIdx.x;
    if (idx < Bv * Nv * Hv) {
        int b = idx / (Nv * Hv);
        int h = idx & (Hv - 1);
        baseQ[idx] += gq[b * Hv + h];
    }
}

// -------------------- greedy decode --------------------
__global__ __launch_bounds__(256)
void decode_kernel(const float* __restrict__ baseL, const float* __restrict__ cross,
                   float* __restrict__ out_tours, float* __restrict__ out_logp)
{
    int idx = blockIdx.x * blockDim.x + threadIdx.x;
    if (idx >= Bv * Nv) return;
    int b = idx >> 8, s = idx & 255;
    unsigned mask[8] = {0, 0, 0, 0, 0, 0, 0, 0};
    mask[s >> 5] |= 1u << (s & 31);
    const float* bl = baseL + ((size_t)b * Nv + s) * Nv;
    int cur = s;
    float logp = 0.f;
    out_tours[(size_t)idx * TOURLEN] = (float)s;
    for (int step = 1; step < TOURLEN; step++) {
        const float* cr = cross + ((size_t)b * Nv + cur) * Nv;
        float mx = -3.4e38f;
        int arg = 0;
        for (int n = 0; n < Nv; n++) {
            bool vis = (mask[n >> 5] >> (n & 31)) & 1u;
            float v = vis ? -1e9f : (__ldg(bl + n) + __ldg(cr + n));
            if (v > mx) { mx = v; arg = n; }
        }
        float sum = 0.f;
        for (int n = 0; n < Nv; n++) {
            bool vis = (mask[n >> 5] >> (n & 31)) & 1u;
            if (!vis) sum += expf(__ldg(bl + n) + __ldg(cr + n) - mx);
        }
        logp -= logf(sum);
        mask[arg >> 5] |= 1u << (arg & 31);
        cur = arg;
        out_tours[(size_t)idx * TOURLEN + step] = (float)arg;
    }
    out_logp[idx] = logp;
}

// -------------------- host orchestration --------------------
extern "C" void kernel_launch(void* const* d_in, const int* in_sizes, int n_in,
                              void* d_out, int out_size)
{
    const float* x      = (const float*)d_in[0];
    const float* init_W = (const float*)d_in[1];
    const float* init_b = (const float*)d_in[2];
    const float* Wqkv   = (const float*)d_in[3];
    const float* bqkv   = (const float*)d_in[4];
    const float* Wo     = (const float*)d_in[5];
    const float* bo     = (const float*)d_in[6];
    const float* W1     = (const float*)d_in[7];
    const float* b1     = (const float*)d_in[8];
    const float* W2     = (const float*)d_in[9];
    const float* b2     = (const float*)d_in[10];
    const float* ln1_g  = (const float*)d_in[11];
    const float* ln1_b  = (const float*)d_in[12];
    const float* ln2_g  = (const float*)d_in[13];
    const float* ln2_b  = (const float*)d_in[14];
    const float* Wquery = (const float*)d_in[15];
    const float* bquery = (const float*)d_in[16];
    const float* Wq     = (const float*)d_in[17];
    const float* Wk     = (const float*)d_in[18];

    float *h, *tmp, *kbuf, *Mbuf, *baseQ, *graph, *gq;
    float *W1q, *W2q, *W3q, *bq2, *baseL, *cross;
    __nv_bfloat16 *hs, *atts, *ffs, *wqkvt, *wot, *w1t, *w2t;
    cudaGetSymbolAddress((void**)&h,     g_h);
    cudaGetSymbolAddress((void**)&tmp,   g_tmp);
    cudaGetSymbolAddress((void**)&kbuf,  g_k);
    cudaGetSymbolAddress((void**)&Mbuf,  g_M);
    cudaGetSymbolAddress((void**)&baseQ, g_baseQ);
    cudaGetSymbolAddress((void**)&graph, g_graph);
    cudaGetSymbolAddress((void**)&gq,    g_gq);
    cudaGetSymbolAddress((void**)&W1q,   g_W1q);
    cudaGetSymbolAddress((void**)&W2q,   g_W2q);
    cudaGetSymbolAddress((void**)&W3q,   g_W3q);
    cudaGetSymbolAddress((void**)&bq2,   g_bq2);
    cudaGetSymbolAddress((void**)&baseL, g_baseL);
    cudaGetSymbolAddress((void**)&cross, g_cross);
    cudaGetSymbolAddress((void**)&hs,    g_hs);
    cudaGetSymbolAddress((void**)&atts,  g_atts);
    cudaGetSymbolAddress((void**)&ffs,   g_ffs);
    cudaGetSymbolAddress((void**)&wqkvt, g_wqkvt);
    cudaGetSymbolAddress((void**)&wot,   g_wot);
    cudaGetSymbolAddress((void**)&w1t,   g_w1t);
    cudaGetSymbolAddress((void**)&w2t,   g_w2t);

    const int MBm = MTOK / 128;

    // ---- weight prep: 4 batched launches (layer = blockIdx.y)
    wprep_all<<<dim3((Hv * 3 * Hv + 255) / 256, Lv), 256>>>(
        Wqkv, wqkvt, Hv, 3 * Hv, (size_t)Hv * 3 * Hv, (size_t)3 * (3 * Hv) * Hv);
    wprep_all<<<dim3((Hv * Hv + 255) / 256, Lv), 256>>>(
        Wo, wot, Hv, Hv, (size_t)Hv * Hv, (size_t)3 * Hv * Hv);
    wprep_all<<<dim3((Hv * DFFv + 255) / 256, Lv), 256>>>(
        W1, w1t, Hv, DFFv, (size_t)Hv * DFFv, (size_t)3 * DFFv * Hv);
    wprep_all<<<dim3((DFFv * Hv + 255) / 256, Lv), 256>>>(
        W2, w2t, DFFv, Hv, (size_t)DFFv * Hv, (size_t)3 * Hv * DFFv);

    // ---- init embedding: h = x @ init_W + init_b  (K=16, fp32), then split
    sgemm_k<128, 0><<<dim3(1, MBm), 256>>>(
        x, init_W, init_b, nullptr, nullptr, nullptr, h, MTOK, Hv, Din);
    split_act<<<(MTOK * Hv + 255) / 256, 256>>>(h, hs, (size_t)MTOK * Hv, HS_STRIDE);

    // ---- encoder layers (HMMA bf16x6 on pre-split planes)
    const size_t WQKV_PS = (size_t)(3 * Hv) * Hv;
    const size_t WO_PS   = (size_t)Hv * Hv;
    const size_t W1_PS   = (size_t)DFFv * Hv;
    const size_t W2_PS   = (size_t)Hv * DFFv;
    for (int l = 0; l < Lv; l++) {
        mma_gemm<2><<<dim3(6, MBm), 256, SMB_BYTES>>>(
            hs, HS_STRIDE, wqkvt + (size_t)l * 3 * WQKV_PS, WQKV_PS,
            bqkv + (size_t)l * 3 * Hv, tmp, nullptr, 0, Hv, 3 * Hv);
        attn_kernel<<<Bv * HEADSv, 256>>>(tmp, atts);
        mma_gemm<0><<<dim3(2, MBm), 256, SMB_BYTES>>>(
            atts, HS_STRIDE, wot + (size_t)l * 3 * WO_PS, WO_PS,
            nullptr, tmp, nullptr, 0, Hv, Hv);
        ln_split<<<MTOK, 128>>>(tmp, bo + (size_t)l * Hv, h,
                                ln1_g + (size_t)l * Hv, ln1_b + (size_t)l * Hv, h, hs);
        mma_gemm<1><<<dim3(DFFv / 64, MBm), 256, SMB_BYTES>>>(
            hs, HS_STRIDE, w1t + (size_t)l * 3 * W1_PS, W1_PS,
            b1 + (size_t)l * DFFv, nullptr, ffs, FF_STRIDE, Hv, DFFv);
        mma_gemm<0><<<dim3(2, MBm), 256, SMB_BYTES>>>(
            ffs, FF_STRIDE, w2t + (size_t)l * 3 * W2_PS, W2_PS,
            nullptr, tmp, nullptr, 0, DFFv, Hv);
        ln_split<<<MTOK, 128>>>(tmp, b2 + (size_t)l * Hv, h,
                                ln2_g + (size_t)l * Hv, ln2_b + (size_t)l * Hv, h, hs);
    }

    // ---- decoder precompute: EXACT R3 fp32 path
    graph_mean<<<Bv, 128>>>(h, graph);
    sgemm_k<128, 0><<<dim3(1, MBm), 256>>>(
        h, Wk, nullptr, nullptr, nullptr, nullptr, kbuf, MTOK, Hv, Hv);

    sgemm_k<64, 0><<<dim3(1, 2), 256>>>(Wquery,               Wq, nullptr, nullptr, nullptr, nullptr, W1q, Hv, Hv, Hv);
    sgemm_k<64, 0><<<dim3(1, 2), 256>>>(Wquery + Hv * Hv,     Wq, nullptr, nullptr, nullptr, nullptr, W2q, Hv, Hv, Hv);
    sgemm_k<64, 0><<<dim3(1, 2), 256>>>(Wquery + 2 * Hv * Hv, Wq, nullptr, nullptr, nullptr, nullptr, W3q, Hv, Hv, Hv);
    vecmat<<<1, 128>>>(bquery, Wq, bq2);

    sgemm_k<64, 0><<<dim3(1, 1), 256>>>(graph, W1q, bq2, nullptr, nullptr, nullptr, gq, Bv, Hv, Hv);
    sgemm_k<128, 0><<<dim3(1, MBm), 256>>>(
        h, W2q, nullptr, nullptr, nullptr, nullptr, baseQ, MTOK, Hv, Hv);
    add_gq<<<(Bv * Nv * Hv + 255) / 256, 256>>>(baseQ, gq);
    sgemm_k<128, 0><<<dim3(1, MBm), 256>>>(
        h, W3q, nullptr, nullptr, nullptr, nullptr, Mbuf, MTOK, Hv, Hv);

    bgemm_nt128<<<dim3(2, 2, Bv), 256>>>(baseQ, kbuf, baseL, LSCALE);
    bgemm_nt128<<<dim3(2, 2, Bv), 256>>>(Mbuf,  kbuf, cross, LSCALE);

    // ---- greedy decode
    float* out = (float*)d_out;
    decode_kernel<<<(Bv * Nv + 255) / 256, 256>>>(baseL, cross, out, out + (size_t)Bv * Nv * TOURLEN);
}

// round 12
// speedup vs baseline: 1.0451x; 1.0331x over previous
#include <cuda_runtime.h>
#include <cuda_bf16.h>
#include <math.h>

#define Bv   64
#define Nv   256
#define Din  16
#define Hv   128
#define Lv   6
#define DFFv 2048
#define HEADSv 8
#define DHv  16
#define TOURLEN 16
#define LSCALE 0.08838834764831845f   /* H^-0.5 */
#define SPLITK 4

// -------------------- device scratch (no allocations allowed) --------------------
__device__ float g_h[Bv*Nv*Hv];
__device__ float g_qkv[Bv*Nv*3*Hv];
__device__ float g_att[Bv*Nv*Hv];
__device__ float g_ff[Bv*Nv*DFFv];
__device__ float g_part[SPLITK*Bv*Nv*Hv];
__device__ float g_k[Bv*Nv*Hv];
__device__ float g_M[Bv*Nv*Hv];
__device__ float g_baseQ[Bv*Nv*Hv];
__device__ float g_graph[Bv*Hv];
__device__ float g_gq[Bv*Hv];
__device__ float g_W1q[Hv*Hv];
__device__ float g_W2q[Hv*Hv];
__device__ float g_W3q[Hv*Hv];
__device__ float g_bq2[Hv];
__device__ float g_baseL[Bv*Nv*Nv];
__device__ float g_cross[Bv*Nv*Nv];

// -------------------- packed fp32x2 helpers (Blackwell) --------------------
__device__ __forceinline__ unsigned long long bcast2(float x) {
    unsigned long long r;
    asm("mov.b64 %0, {%1, %1};" : "=l"(r) : "f"(x));
    return r;
}
__device__ __forceinline__ void fma2(unsigned long long& d,
                                     unsigned long long a, unsigned long long b) {
    asm("fma.rn.f32x2 %0, %1, %2, %0;" : "+l"(d) : "l"(a), "l"(b));
}
__device__ __forceinline__ float2 unpk2(unsigned long long v) {
    float lo, hi;
    asm("mov.b64 {%0, %1}, %2;" : "=f"(lo), "=f"(hi) : "l"(v));
    return make_float2(lo, hi);
}

// ============================================================================
// SGEMM (R3-proven), BN=128 fixed, BK=16, 256 threads, double-buffered, f32x2.
// BM=128 -> 8x8 per-thread tile;  BM=64 -> 4x8.  K-range [kbeg,kend) for split-K.
// EPI: 0 = optional bias
//      1 = bias + relu
//      2 = bias + residual + LayerNorm over the 128-wide row (requires N==128)
// ============================================================================
template<int BM, int EPI>
__global__ __launch_bounds__(256, 2)
void sgemm_k(const float* __restrict__ A, const float* __restrict__ B,
             const float* __restrict__ bias, const float* __restrict__ res,
             const float* __restrict__ lng, const float* __restrict__ lnb,
             float* __restrict__ C, int M, int N, int K, int kbeg, int kend)
{
    constexpr int TM = BM / 16;                 // rows per thread
    constexpr int TP = TM / 2;                  // row-pairs per thread
    constexpr int NA = (BM * 16) / 1024;        // float4 A-loads per thread
    __shared__ __align__(16) float As[2][16][BM];
    __shared__ __align__(16) float Bs[2][16][128];

    const int tid = threadIdx.x;
    const int tx = tid & 15, ty = tid >> 4;
    const int bm = blockIdx.y * BM;
    const int bn = blockIdx.x * 128;

    const float* Ab = A + (size_t)bm * K;
    const float* Bb = B + bn;

    float4 ra[NA], rb[2];

    // ---- prologue: global load of first tile
    #pragma unroll
    for (int i = 0; i < NA; i++) {
        int lin = tid + i * 256;
        int r = lin >> 2, c4 = (lin & 3) << 2;
        ra[i] = *(const float4*)(Ab + (size_t)r * K + kbeg + c4);
    }
    #pragma unroll
    for (int i = 0; i < 2; i++) {
        int lin = tid + i * 256;
        int r = lin >> 5, c4 = (lin & 31) << 2;
        rb[i] = *(const float4*)(Bb + (size_t)(kbeg + r) * N + c4);
    }
    #pragma unroll
    for (int i = 0; i < NA; i++) {
        int lin = tid + i * 256;
        int r = lin >> 2, c4 = (lin & 3) << 2;
        As[0][c4 + 0][r] = ra[i].x; As[0][c4 + 1][r] = ra[i].y;
        As[0][c4 + 2][r] = ra[i].z; As[0][c4 + 3][r] = ra[i].w;
    }
    #pragma unroll
    for (int i = 0; i < 2; i++) {
        int lin = tid + i * 256;
        int r = lin >> 5, c4 = (lin & 31) << 2;
        *(float4*)&Bs[0][r][c4] = rb[i];
    }
    __syncthreads();

    unsigned long long acc[TP][8];
    #pragma unroll
    for (int i = 0; i < TP; i++)
        #pragma unroll
        for (int j = 0; j < 8; j++) acc[i][j] = 0ull;

    int buf = 0;
    for (int k0 = kbeg; k0 < kend; k0 += 16) {
        const bool has_next = (k0 + 16) < kend;
        if (has_next) {
            #pragma unroll
            for (int i = 0; i < NA; i++) {
                int lin = tid + i * 256;
                int r = lin >> 2, c4 = (lin & 3) << 2;
                ra[i] = *(const float4*)(Ab + (size_t)r * K + k0 + 16 + c4);
            }
            #pragma unroll
            for (int i = 0; i < 2; i++) {
                int lin = tid + i * 256;
                int r = lin >> 5, c4 = (lin & 31) << 2;
                rb[i] = *(const float4*)(Bb + (size_t)(k0 + 16 + r) * N + c4);
            }
        }
        #pragma unroll
        for (int kk = 0; kk < 16; kk++) {
            unsigned long long a2[TP];
            #pragma unroll
            for (int i = 0; i < TP; i += 2) {
                ulonglong2 t = *(const ulonglong2*)&As[buf][kk][ty * TM + i * 2];
                a2[i] = t.x; a2[i + 1] = t.y;
            }
            float4 bf0 = *(const float4*)&Bs[buf][kk][tx * 8];
            float4 bf1 = *(const float4*)&Bs[buf][kk][tx * 8 + 4];
            unsigned long long bb[8];
            bb[0] = bcast2(bf0.x); bb[1] = bcast2(bf0.y);
            bb[2] = bcast2(bf0.z); bb[3] = bcast2(bf0.w);
            bb[4] = bcast2(bf1.x); bb[5] = bcast2(bf1.y);
            bb[6] = bcast2(bf1.z); bb[7] = bcast2(bf1.w);
            #pragma unroll
            for (int i = 0; i < TP; i++)
                #pragma unroll
                for (int j = 0; j < 8; j++) fma2(acc[i][j], a2[i], bb[j]);
        }
        if (has_next) {
            int nb = buf ^ 1;
            #pragma unroll
            for (int i = 0; i < NA; i++) {
                int lin = tid + i * 256;
                int r = lin >> 2, c4 = (lin & 3) << 2;
                As[nb][c4 + 0][r] = ra[i].x; As[nb][c4 + 1][r] = ra[i].y;
                As[nb][c4 + 2][r] = ra[i].z; As[nb][c4 + 3][r] = ra[i].w;
            }
            #pragma unroll
            for (int i = 0; i < 2; i++) {
                int lin = tid + i * 256;
                int r = lin >> 5, c4 = (lin & 31) << 2;
                *(float4*)&Bs[nb][r][c4] = rb[i];
            }
            __syncthreads();
            buf = nb;
        }
    }

    // ---- epilogue
    float bv[8] = {0.f,0.f,0.f,0.f,0.f,0.f,0.f,0.f};
    if (bias) {
        *(float4*)&bv[0] = *(const float4*)(bias + bn + tx * 8);
        *(float4*)&bv[4] = *(const float4*)(bias + bn + tx * 8 + 4);
    }

    if (EPI == 2) {
        float gv[8], be[8];
        *(float4*)&gv[0] = *(const float4*)(lng + tx * 8);
        *(float4*)&gv[4] = *(const float4*)(lng + tx * 8 + 4);
        *(float4*)&be[0] = *(const float4*)(lnb + tx * 8);
        *(float4*)&be[4] = *(const float4*)(lnb + tx * 8 + 4);
        #pragma unroll
        for (int ip = 0; ip < TP; ip++) {
            #pragma unroll
            for (int e = 0; e < 2; e++) {
                int row = bm + ty * TM + ip * 2 + e;
                const float* rp = res + (size_t)row * 128 + tx * 8;
                float4 r0 = *(const float4*)rp;
                float4 r1 = *(const float4*)(rp + 4);
                float v[8];
                #pragma unroll
                for (int j = 0; j < 8; j++) {
                    float2 p = unpk2(acc[ip][j]);
                    v[j] = (e == 0 ? p.x : p.y) + bv[j];
                }
                v[0] += r0.x; v[1] += r0.y; v[2] += r0.z; v[3] += r0.w;
                v[4] += r1.x; v[5] += r1.y; v[6] += r1.z; v[7] += r1.w;
                float s = 0.f, s2 = 0.f;
                #pragma unroll
                for (int j = 0; j < 8; j++) { s += v[j]; s2 += v[j] * v[j]; }
                #pragma unroll
                for (int m = 8; m >= 1; m >>= 1) {
                    s  += __shfl_xor_sync(0xffffffffu, s,  m);
                    s2 += __shfl_xor_sync(0xffffffffu, s2, m);
                }
                float mu  = s * (1.f / 128.f);
                float var = s2 * (1.f / 128.f) - mu * mu;
                float rs  = rsqrtf(var + 1e-5f);
                float o[8];
                #pragma unroll
                for (int j = 0; j < 8; j++) o[j] = (v[j] - mu) * rs * gv[j] + be[j];
                float* cp = C + (size_t)row * 128 + tx * 8;
                *(float4*)cp       = *(float4*)&o[0];
                *(float4*)(cp + 4) = *(float4*)&o[4];
            }
        }
    } else {
        #pragma unroll
        for (int ip = 0; ip < TP; ip++) {
            #pragma unroll
            for (int e = 0; e < 2; e++) {
                int row = bm + ty * TM + ip * 2 + e;
                float o[8];
                #pragma unroll
                for (int j = 0; j < 8; j++) {
                    float2 p = unpk2(acc[ip][j]);
                    float v = (e == 0 ? p.x : p.y) + bv[j];
                    if (EPI == 1) v = fmaxf(v, 0.f);
                    o[j] = v;
                }
                float* cp = C + (size_t)row * N + bn + tx * 8;
                *(float4*)cp       = *(float4*)&o[0];
                *(float4*)(cp + 4) = *(float4*)&o[4];
            }
        }
    }
}

// ---- split-K reduce + bias + residual + LayerNorm (R4-proven)
__global__ __launch_bounds__(128)
void reduce_ln(const float* __restrict__ part, const float* __restrict__ bias,
               const float* __restrict__ res, const float* __restrict__ g,
               const float* __restrict__ be, float* __restrict__ out)
{
    const int row = blockIdx.x, t = threadIdx.x;
    const size_t stride = (size_t)Bv * Nv * Hv;
    float v = part[(size_t)row * Hv + t];
    #pragma unroll
    for (int z = 1; z < SPLITK; z++) v += part[z * stride + (size_t)row * Hv + t];
    v += bias[t] + res[(size_t)row * Hv + t];

    __shared__ float ws[4], ws2[4];
    int lane = t & 31, wid = t >> 5;
    float s = v, s2 = v * v;
    #pragma unroll
    for (int o = 16; o > 0; o >>= 1) {
        s  += __shfl_xor_sync(0xffffffffu, s,  o);
        s2 += __shfl_xor_sync(0xffffffffu, s2, o);
    }
    if (lane == 0) { ws[wid] = s; ws2[wid] = s2; }
    __syncthreads();
    float mu  = (ws[0] + ws[1] + ws[2] + ws[3]) * (1.f / Hv);
    float var = (ws2[0] + ws2[1] + ws2[2] + ws2[3]) * (1.f / Hv) - mu * mu;
    out[(size_t)row * Hv + t] = (v - mu) * rsqrtf(var + 1e-5f) * g[t] + be[t];
}

// ============================================================================
// Batched NT GEMM (R3-proven): C[b,i,j] = scale * A[b,i,:].Kb[b,j,:] (K=H=128)
// ============================================================================
__global__ __launch_bounds__(256, 2)
void bgemm_nt128(const float* __restrict__ A, const float* __restrict__ Kb,
                 float* __restrict__ C, float scale)
{
    __shared__ __align__(16) float As[2][16][128];
    __shared__ __align__(16) float Bs[2][16][128];
    const int tid = threadIdx.x;
    const int tx = tid & 15, ty = tid >> 4;
    const int b = blockIdx.z;
    const int i0 = blockIdx.y * 128, j0 = blockIdx.x * 128;

    const float* Ab = A  + ((size_t)b * Nv + i0) * Hv;
    const float* Kp = Kb + ((size_t)b * Nv + j0) * Hv;

    float4 ra[2], rb[2];
    #pragma unroll
    for (int i = 0; i < 2; i++) {
        int lin = tid + i * 256;
        int r = lin >> 2, c4 = (lin & 3) << 2;
        ra[i] = *(const float4*)(Ab + (size_t)r * Hv + c4);
        rb[i] = *(const float4*)(Kp + (size_t)r * Hv + c4);
    }
    #pragma unroll
    for (int i = 0; i < 2; i++) {
        int lin = tid + i * 256;
        int r = lin >> 2, c4 = (lin & 3) << 2;
        As[0][c4+0][r] = ra[i].x; As[0][c4+1][r] = ra[i].y;
        As[0][c4+2][r] = ra[i].z; As[0][c4+3][r] = ra[i].w;
        Bs[0][c4+0][r] = rb[i].x; Bs[0][c4+1][r] = rb[i].y;
        Bs[0][c4+2][r] = rb[i].z; Bs[0][c4+3][r] = rb[i].w;
    }
    __syncthreads();

    unsigned long long acc[4][8];
    #pragma unroll
    for (int i = 0; i < 4; i++)
        #pragma unroll
        for (int j = 0; j < 8; j++) acc[i][j] = 0ull;

    int buf = 0;
    for (int k0 = 0; k0 < Hv; k0 += 16) {
        const bool has_next = (k0 + 16) < Hv;
        if (has_next) {
            #pragma unroll
            for (int i = 0; i < 2; i++) {
                int lin = tid + i * 256;
                int r = lin >> 2, c4 = (lin & 3) << 2;
                ra[i] = *(const float4*)(Ab + (size_t)r * Hv + k0 + 16 + c4);
                rb[i] = *(const float4*)(Kp + (size_t)r * Hv + k0 + 16 + c4);
            }
        }
        #pragma unroll
        for (int kk = 0; kk < 16; kk++) {
            unsigned long long a2[4];
            {
                ulonglong2 t0 = *(const ulonglong2*)&As[buf][kk][ty * 8];
                ulonglong2 t1 = *(const ulonglong2*)&As[buf][kk][ty * 8 + 4];
                a2[0] = t0.x; a2[1] = t0.y; a2[2] = t1.x; a2[3] = t1.y;
            }
            float4 bf0 = *(const float4*)&Bs[buf][kk][tx * 8];
            float4 bf1 = *(const float4*)&Bs[buf][kk][tx * 8 + 4];
            unsigned long long bb[8];
            bb[0] = bcast2(bf0.x); bb[1] = bcast2(bf0.y);
            bb[2] = bcast2(bf0.z); bb[3] = bcast2(bf0.w);
            bb[4] = bcast2(bf1.x); bb[5] = bcast2(bf1.y);
            bb[6] = bcast2(bf1.z); bb[7] = bcast2(bf1.w);
            #pragma unroll
            for (int i = 0; i < 4; i++)
                #pragma unroll
                for (int j = 0; j < 8; j++) fma2(acc[i][j], a2[i], bb[j]);
        }
        if (has_next) {
            int nb = buf ^ 1;
            #pragma unroll
            for (int i = 0; i < 2; i++) {
                int lin = tid + i * 256;
                int r = lin >> 2, c4 = (lin & 3) << 2;
                As[nb][c4+0][r] = ra[i].x; As[nb][c4+1][r] = ra[i].y;
                As[nb][c4+2][r] = ra[i].z; As[nb][c4+3][r] = ra[i].w;
                Bs[nb][c4+0][r] = rb[i].x; Bs[nb][c4+1][r] = rb[i].y;
                Bs[nb][c4+2][r] = rb[i].z; Bs[nb][c4+3][r] = rb[i].w;
            }
            __syncthreads();
            buf = nb;
        }
    }

    #pragma unroll
    for (int ip = 0; ip < 4; ip++) {
        #pragma unroll
        for (int e = 0; e < 2; e++) {
            float* cp = C + ((size_t)b * Nv + i0 + ty * 8 + ip * 2 + e) * Nv + j0 + tx * 8;
            float o[8];
            #pragma unroll
            for (int j = 0; j < 8; j++) {
                float2 p = unpk2(acc[ip][j]);
                o[j] = scale * (e == 0 ? p.x : p.y);
            }
            *(float4*)cp       = *(float4*)&o[0];
            *(float4*)(cp + 4) = *(float4*)&o[4];
        }
    }
}

// -------------------- fused MHA (flash-style, dh=16, N=256) --------------------
__global__ __launch_bounds__(256)
void attn_kernel(const float* __restrict__ qkv, float* __restrict__ out)
{
    int b = blockIdx.x / HEADSv, hd = blockIdx.x % HEADSv;
    __shared__ float Ks[Nv][DHv];
    __shared__ float Vs[Nv][DHv];
    int t = threadIdx.x;
    const float* base = qkv + (size_t)b * Nv * (3 * Hv);
    {
        const float* krow = base + (size_t)t * (3 * Hv) + Hv + hd * DHv;
        const float* vrow = base + (size_t)t * (3 * Hv) + 2 * Hv + hd * DHv;
        #pragma unroll
        for (int c = 0; c < 4; c++) {
            float4 kv4 = *(const float4*)(krow + c * 4);
            Ks[t][c * 4 + 0] = kv4.x; Ks[t][c * 4 + 1] = kv4.y;
            Ks[t][c * 4 + 2] = kv4.z; Ks[t][c * 4 + 3] = kv4.w;
            float4 vv4 = *(const float4*)(vrow + c * 4);
            Vs[t][c * 4 + 0] = vv4.x; Vs[t][c * 4 + 1] = vv4.y;
            Vs[t][c * 4 + 2] = vv4.z; Vs[t][c * 4 + 3] = vv4.w;
        }
    }
    __syncthreads();

    float q[DHv];
    {
        const float* qrow = base + (size_t)t * (3 * Hv) + hd * DHv;
        #pragma unroll
        for (int d = 0; d < DHv; d++) q[d] = qrow[d];
    }
    float m = -INFINITY, sum = 0.f, acc[DHv];
    #pragma unroll
    for (int d = 0; d < DHv; d++) acc[d] = 0.f;

    for (int j = 0; j < Nv; j++) {
        float s = 0.f;
        #pragma unroll
        for (int d = 0; d < DHv; d++) s += q[d] * Ks[j][d];
        s *= 0.25f;
        float mnew = fmaxf(m, s);
        float corr = expf(m - mnew);
        float p = expf(s - mnew);
        sum = sum * corr + p;
        #pragma unroll
        for (int d = 0; d < DHv; d++) acc[d] = acc[d] * corr + p * Vs[j][d];
        m = mnew;
    }
    float inv = 1.f / sum;
    float* orow = out + ((size_t)b * Nv + t) * Hv + hd * DHv;
    #pragma unroll
    for (int d = 0; d < DHv; d++) orow[d] = acc[d] * inv;
}

// -------------------- graph mean over N --------------------
__global__ __launch_bounds__(128)
void graph_mean(const float* __restrict__ node, float* __restrict__ graph)
{
    int b = blockIdx.x, h = threadIdx.x;
    float s = 0.f;
    for (int n = 0; n < Nv; n++) s += node[((size_t)b * Nv + n) * Hv + h];
    graph[b * Hv + h] = s * (1.f / Nv);
}

// -------------------- bq2 = bquery @ Wq --------------------
__global__ __launch_bounds__(128)
void vecmat(const float* __restrict__ v, const float* __restrict__ W, float* __restrict__ out)
{
    int j = threadIdx.x;
    float s = 0.f;
    for (int i = 0; i < Hv; i++) s += v[i] * W[i * Hv + j];
    out[j] = s;
}

// -------------------- baseQ += gq[b] --------------------
__global__ void add_gq(float* __restrict__ baseQ, const float* __restrict__ gq)
{
    int idx = blockIdx.x * blockDim.x + threadIdx.x;
    if (idx < Bv * Nv * Hv) {
        int b = idx / (Nv * Hv);
        int h = idx & (Hv - 1);
        baseQ[idx] += gq[b * Hv + h];
    }
}

// -------------------- greedy decode: one thread per (b,s) tour --------------------
__global__ __launch_bounds__(256)
void decode_kernel(const float* __restrict__ baseL, const float* __restrict__ cross,
                   float* __restrict__ out_tours, float* __restrict__ out_logp)
{
    int idx = blockIdx.x * blockDim.x + threadIdx.x;
    if (idx >= Bv * Nv) return;
    int b = idx >> 8, s = idx & 255;
    unsigned mask[8] = {0, 0, 0, 0, 0, 0, 0, 0};
    mask[s >> 5] |= 1u << (s & 31);
    const float* bl = baseL + ((size_t)b * Nv + s) * Nv;
    int cur = s;
    float logp = 0.f;
    out_tours[(size_t)idx * TOURLEN] = (float)s;
    for (int step = 1; step < TOURLEN; step++) {
        const float* cr = cross + ((size_t)b * Nv + cur) * Nv;
        float mx = -3.4e38f;
        int arg = 0;
        for (int n = 0; n < Nv; n++) {
            bool vis = (mask[n >> 5] >> (n & 31)) & 1u;
            float v = vis ? -1e9f : (__ldg(bl + n) + __ldg(cr + n));
            if (v > mx) { mx = v; arg = n; }
        }
        float sum = 0.f;
        for (int n = 0; n < Nv; n++) {
            bool vis = (mask[n >> 5] >> (n & 31)) & 1u;
            if (!vis) sum += expf(__ldg(bl + n) + __ldg(cr + n) - mx);
        }
        logp -= logf(sum);
        mask[arg >> 5] |= 1u << (arg & 31);
        cur = arg;
        out_tours[(size_t)idx * TOURLEN + step] = (float)arg;
    }
    out_logp[idx] = logp;
}

// -------------------- host orchestration --------------------
extern "C" void kernel_launch(void* const* d_in, const int* in_sizes, int n_in,
                              void* d_out, int out_size)
{
    const float* x      = (const float*)d_in[0];
    const float* init_W = (const float*)d_in[1];
    const float* init_b = (const float*)d_in[2];
    const float* Wqkv   = (const float*)d_in[3];
    const float* bqkv   = (const float*)d_in[4];
    const float* Wo     = (const float*)d_in[5];
    const float* bo     = (const float*)d_in[6];
    const float* W1     = (const float*)d_in[7];
    const float* b1     = (const float*)d_in[8];
    const float* W2     = (const float*)d_in[9];
    const float* b2     = (const float*)d_in[10];
    const float* ln1_g  = (const float*)d_in[11];
    const float* ln1_b  = (const float*)d_in[12];
    const float* ln2_g  = (const float*)d_in[13];
    const float* ln2_b  = (const float*)d_in[14];
    const float* Wquery = (const float*)d_in[15];
    const float* bquery = (const float*)d_in[16];
    const float* Wq     = (const float*)d_in[17];
    const float* Wk     = (const float*)d_in[18];

    float *h, *qkv, *att, *ff, *part, *kbuf, *Mbuf, *baseQ, *graph, *gq;
    float *W1q, *W2q, *W3q, *bq2, *baseL, *cross;
    cudaGetSymbolAddress((void**)&h,     g_h);
    cudaGetSymbolAddress((void**)&qkv,   g_qkv);
    cudaGetSymbolAddress((void**)&att,   g_att);
    cudaGetSymbolAddress((void**)&ff,    g_ff);
    cudaGetSymbolAddress((void**)&part,  g_part);
    cudaGetSymbolAddress((void**)&kbuf,  g_k);
    cudaGetSymbolAddress((void**)&Mbuf,  g_M);
    cudaGetSymbolAddress((void**)&baseQ, g_baseQ);
    cudaGetSymbolAddress((void**)&graph, g_graph);
    cudaGetSymbolAddress((void**)&gq,    g_gq);
    cudaGetSymbolAddress((void**)&W1q,   g_W1q);
    cudaGetSymbolAddress((void**)&W2q,   g_W2q);
    cudaGetSymbolAddress((void**)&W3q,   g_W3q);
    cudaGetSymbolAddress((void**)&bq2,   g_bq2);
    cudaGetSymbolAddress((void**)&baseL, g_baseL);
    cudaGetSymbolAddress((void**)&cross, g_cross);

    const int Mtok = Bv * Nv;    // 16384
    const int MB = Mtok / 128;   // 128 row-blocks

    // ---- init embedding: h = x @ init_W + init_b  (K=16)
    sgemm_k<128, 0><<<dim3(1, MB), 256>>>(
        x, init_W, init_b, nullptr, nullptr, nullptr, h, Mtok, Hv, Din, 0, Din);

    // ---- encoder layers
    for (int l = 0; l < Lv; l++) {
        sgemm_k<128, 0><<<dim3(3, MB), 256>>>(
            h, Wqkv + (size_t)l * Hv * 3 * Hv, bqkv + (size_t)l * 3 * Hv,
            nullptr, nullptr, nullptr, qkv, Mtok, 3 * Hv, Hv, 0, Hv);
        attn_kernel<<<Bv * HEADSv, 256>>>(qkv, att);
        // h = LN(h + att @ Wo + bo)   (fused, K=128 single pass)
        sgemm_k<128, 2><<<dim3(1, MB), 256>>>(
            att, Wo + (size_t)l * Hv * Hv, bo + (size_t)l * Hv,
            h, ln1_g + (size_t)l * Hv, ln1_b + (size_t)l * Hv, h, Mtok, Hv, Hv, 0, Hv);
        sgemm_k<128, 1><<<dim3(DFFv / 128, MB), 256>>>(
            h, W1 + (size_t)l * Hv * DFFv, b1 + (size_t)l * DFFv,
            nullptr, nullptr, nullptr, ff, Mtok, DFFv, Hv, 0, Hv);
        // W2 whale: split-K=4 partials (grid 512 -> 2 CTAs/SM), then reduce+LN
        for (int z = 0; z < SPLITK; z++) {
            sgemm_k<128, 0><<<dim3(1, MB), 256>>>(
                ff, W2 + (size_t)l * DFFv * Hv, nullptr, nullptr, nullptr, nullptr,
                part + (size_t)z * Mtok * Hv, Mtok, Hv, DFFv,
                z * (DFFv / SPLITK), (z + 1) * (DFFv / SPLITK));
        }
        reduce_ln<<<Mtok, 128>>>(part, b2 + (size_t)l * Hv, h,
                                 ln2_g + (size_t)l * Hv, ln2_b + (size_t)l * Hv, h);
    }

    // ---- decoder precompute (exact R3 fp32 path)
    graph_mean<<<Bv, 128>>>(h, graph);
    sgemm_k<128, 0><<<dim3(1, MB), 256>>>(
        h, Wk, nullptr, nullptr, nullptr, nullptr, kbuf, Mtok, Hv, Hv, 0, Hv);

    sgemm_k<64, 0><<<dim3(1, 2), 256>>>(Wquery,               Wq, nullptr, nullptr, nullptr, nullptr, W1q, Hv, Hv, Hv, 0, Hv);
    sgemm_k<64, 0><<<dim3(1, 2), 256>>>(Wquery + Hv * Hv,     Wq, nullptr, nullptr, nullptr, nullptr, W2q, Hv, Hv, Hv, 0, Hv);
    sgemm_k<64, 0><<<dim3(1, 2), 256>>>(Wquery + 2 * Hv * Hv, Wq, nullptr, nullptr, nullptr, nullptr, W3q, Hv, Hv, Hv, 0, Hv);
    vecmat<<<1, 128>>>(bquery, Wq, bq2);

    sgemm_k<64, 0><<<dim3(1, 1), 256>>>(graph, W1q, bq2, nullptr, nullptr, nullptr, gq, Bv, Hv, Hv, 0, Hv);
    sgemm_k<128, 0><<<dim3(1, MB), 256>>>(
        h, W2q, nullptr, nullptr, nullptr, nullptr, baseQ, Mtok, Hv, Hv, 0, Hv);
    add_gq<<<(Bv * Nv * Hv + 255) / 256, 256>>>(baseQ, gq);
    sgemm_k<128, 0><<<dim3(1, MB), 256>>>(
        h, W3q, nullptr, nullptr, nullptr, nullptr, Mbuf, Mtok, Hv, Hv, 0, Hv);

    bgemm_nt128<<<dim3(2, 2, Bv), 256>>>(baseQ, kbuf, baseL, LSCALE);
    bgemm_nt128<<<dim3(2, 2, Bv), 256>>>(Mbuf,  kbuf, cross, LSCALE);

    // ---- greedy decode
    float* out = (float*)d_out;
    decode_kernel<<<(Bv * Nv + 255) / 256, 256>>>(baseL, cross, out, out + (size_t)Bv * Nv * TOURLEN);
}

// round 13
// speedup vs baseline: 1.1205x; 1.0721x over previous
#include <cuda_runtime.h>
#include <cuda_bf16.h>
#include <math.h>

#define Bv   64
#define Nv   256
#define Din  16
#define Hv   128
#define Lv   6
#define DFFv 2048
#define HEADSv 8
#define DHv  16
#define TOURLEN 16
#define LSCALE 0.08838834764831845f   /* H^-0.5 */
#define SPLITK 4

// -------------------- device scratch (no allocations allowed) --------------------
__device__ float g_h[Bv*Nv*Hv];
__device__ float g_qkv[Bv*Nv*3*Hv];
__device__ float g_att[Bv*Nv*Hv];
__device__ float g_ff[Bv*Nv*DFFv];
__device__ float g_part[SPLITK*Bv*Nv*Hv];
__device__ float g_k[Bv*Nv*Hv];
__device__ float g_M[Bv*Nv*Hv];
__device__ float g_baseQ[Bv*Nv*Hv];
__device__ float g_graph[Bv*Hv];
__device__ float g_gq[Bv*Hv];
__device__ float g_W1q[Hv*Hv];
__device__ float g_W2q[Hv*Hv];
__device__ float g_W3q[Hv*Hv];
__device__ float g_bq2[Hv];
__device__ float g_baseL[Bv*Nv*Nv];
__device__ float g_cross[Bv*Nv*Nv];

// -------------------- packed fp32x2 helpers (Blackwell) --------------------
__device__ __forceinline__ unsigned long long bcast2(float x) {
    unsigned long long r;
    asm("mov.b64 %0, {%1, %1};" : "=l"(r) : "f"(x));
    return r;
}
__device__ __forceinline__ void fma2(unsigned long long& d,
                                     unsigned long long a, unsigned long long b) {
    asm("fma.rn.f32x2 %0, %1, %2, %0;" : "+l"(d) : "l"(a), "l"(b));
}
__device__ __forceinline__ float2 unpk2(unsigned long long v) {
    float lo, hi;
    asm("mov.b64 {%0, %1}, %2;" : "=f"(lo), "=f"(hi) : "l"(v));
    return make_float2(lo, hi);
}

// ============================================================================
// SGEMM (R3-proven core), BN=128, BK=16, 256 threads, double-buffered, f32x2.
// blockIdx.z = K-slice index: kbeg = z*K/gridDim.z, C += z*strCz.
// EPI: 0 = optional bias
//      1 = bias + relu
//      2 = bias + residual + LayerNorm over the 128-wide row (requires N==128)
// ============================================================================
template<int BM, int EPI>
__global__ __launch_bounds__(256, 2)
void sgemm_k(const float* __restrict__ A, const float* __restrict__ B,
             const float* __restrict__ bias, const float* __restrict__ res,
             const float* __restrict__ lng, const float* __restrict__ lnb,
             float* __restrict__ C, int M, int N, int K, size_t strCz)
{
    constexpr int TM = BM / 16;
    constexpr int TP = TM / 2;
    constexpr int NA = (BM * 16) / 1024;
    __shared__ __align__(16) float As[2][16][BM];
    __shared__ __align__(16) float Bs[2][16][128];

    const int tid = threadIdx.x;
    const int tx = tid & 15, ty = tid >> 4;
    const int bm = blockIdx.y * BM;
    const int bn = blockIdx.x * 128;
    const int kslice = K / gridDim.z;
    const int kbeg = blockIdx.z * kslice;
    const int kend = kbeg + kslice;
    C += (size_t)blockIdx.z * strCz;

    const float* Ab = A + (size_t)bm * K;
    const float* Bb = B + bn;

    float4 ra[NA], rb[2];

    #pragma unroll
    for (int i = 0; i < NA; i++) {
        int lin = tid + i * 256;
        int r = lin >> 2, c4 = (lin & 3) << 2;
        ra[i] = *(const float4*)(Ab + (size_t)r * K + kbeg + c4);
    }
    #pragma unroll
    for (int i = 0; i < 2; i++) {
        int lin = tid + i * 256;
        int r = lin >> 5, c4 = (lin & 31) << 2;
        rb[i] = *(const float4*)(Bb + (size_t)(kbeg + r) * N + c4);
    }
    #pragma unroll
    for (int i = 0; i < NA; i++) {
        int lin = tid + i * 256;
        int r = lin >> 2, c4 = (lin & 3) << 2;
        As[0][c4 + 0][r] = ra[i].x; As[0][c4 + 1][r] = ra[i].y;
        As[0][c4 + 2][r] = ra[i].z; As[0][c4 + 3][r] = ra[i].w;
    }
    #pragma unroll
    for (int i = 0; i < 2; i++) {
        int lin = tid + i * 256;
        int r = lin >> 5, c4 = (lin & 31) << 2;
        *(float4*)&Bs[0][r][c4] = rb[i];
    }
    __syncthreads();

    unsigned long long acc[TP][8];
    #pragma unroll
    for (int i = 0; i < TP; i++)
        #pragma unroll
        for (int j = 0; j < 8; j++) acc[i][j] = 0ull;

    int buf = 0;
    for (int k0 = kbeg; k0 < kend; k0 += 16) {
        const bool has_next = (k0 + 16) < kend;
        if (has_next) {
            #pragma unroll
            for (int i = 0; i < NA; i++) {
                int lin = tid + i * 256;
                int r = lin >> 2, c4 = (lin & 3) << 2;
                ra[i] = *(const float4*)(Ab + (size_t)r * K + k0 + 16 + c4);
            }
            #pragma unroll
            for (int i = 0; i < 2; i++) {
                int lin = tid + i * 256;
                int r = lin >> 5, c4 = (lin & 31) << 2;
                rb[i] = *(const float4*)(Bb + (size_t)(k0 + 16 + r) * N + c4);
            }
        }
        #pragma unroll
        for (int kk = 0; kk < 16; kk++) {
            unsigned long long a2[TP];
            #pragma unroll
            for (int i = 0; i < TP; i += 2) {
                ulonglong2 t = *(const ulonglong2*)&As[buf][kk][ty * TM + i * 2];
                a2[i] = t.x; a2[i + 1] = t.y;
            }
            float4 bf0 = *(const float4*)&Bs[buf][kk][tx * 8];
            float4 bf1 = *(const float4*)&Bs[buf][kk][tx * 8 + 4];
            unsigned long long bb[8];
            bb[0] = bcast2(bf0.x); bb[1] = bcast2(bf0.y);
            bb[2] = bcast2(bf0.z); bb[3] = bcast2(bf0.w);
            bb[4] = bcast2(bf1.x); bb[5] = bcast2(bf1.y);
            bb[6] = bcast2(bf1.z); bb[7] = bcast2(bf1.w);
            #pragma unroll
            for (int i = 0; i < TP; i++)
                #pragma unroll
                for (int j = 0; j < 8; j++) fma2(acc[i][j], a2[i], bb[j]);
        }
        if (has_next) {
            int nb = buf ^ 1;
            #pragma unroll
            for (int i = 0; i < NA; i++) {
                int lin = tid + i * 256;
                int r = lin >> 2, c4 = (lin & 3) << 2;
                As[nb][c4 + 0][r] = ra[i].x; As[nb][c4 + 1][r] = ra[i].y;
                As[nb][c4 + 2][r] = ra[i].z; As[nb][c4 + 3][r] = ra[i].w;
            }
            #pragma unroll
            for (int i = 0; i < 2; i++) {
                int lin = tid + i * 256;
                int r = lin >> 5, c4 = (lin & 31) << 2;
                *(float4*)&Bs[nb][r][c4] = rb[i];
            }
            __syncthreads();
            buf = nb;
        }
    }

    // ---- epilogue
    float bv[8] = {0.f,0.f,0.f,0.f,0.f,0.f,0.f,0.f};
    if (bias) {
        *(float4*)&bv[0] = *(const float4*)(bias + bn + tx * 8);
        *(float4*)&bv[4] = *(const float4*)(bias + bn + tx * 8 + 4);
    }

    if (EPI == 2) {
        float gv[8], be[8];
        *(float4*)&gv[0] = *(const float4*)(lng + tx * 8);
        *(float4*)&gv[4] = *(const float4*)(lng + tx * 8 + 4);
        *(float4*)&be[0] = *(const float4*)(lnb + tx * 8);
        *(float4*)&be[4] = *(const float4*)(lnb + tx * 8 + 4);
        #pragma unroll
        for (int ip = 0; ip < TP; ip++) {
            #pragma unroll
            for (int e = 0; e < 2; e++) {
                int row = bm + ty * TM + ip * 2 + e;
                const float* rp = res + (size_t)row * 128 + tx * 8;
                float4 r0 = *(const float4*)rp;
                float4 r1 = *(const float4*)(rp + 4);
                float v[8];
                #pragma unroll
                for (int j = 0; j < 8; j++) {
                    float2 p = unpk2(acc[ip][j]);
                    v[j] = (e == 0 ? p.x : p.y) + bv[j];
                }
                v[0] += r0.x; v[1] += r0.y; v[2] += r0.z; v[3] += r0.w;
                v[4] += r1.x; v[5] += r1.y; v[6] += r1.z; v[7] += r1.w;
                float s = 0.f, s2 = 0.f;
                #pragma unroll
                for (int j = 0; j < 8; j++) { s += v[j]; s2 += v[j] * v[j]; }
                #pragma unroll
                for (int m = 8; m >= 1; m >>= 1) {
                    s  += __shfl_xor_sync(0xffffffffu, s,  m);
                    s2 += __shfl_xor_sync(0xffffffffu, s2, m);
                }
                float mu  = s * (1.f / 128.f);
                float var = s2 * (1.f / 128.f) - mu * mu;
                float rs  = rsqrtf(var + 1e-5f);
                float o[8];
                #pragma unroll
                for (int j = 0; j < 8; j++) o[j] = (v[j] - mu) * rs * gv[j] + be[j];
                float* cp = C + (size_t)row * 128 + tx * 8;
                *(float4*)cp       = *(float4*)&o[0];
                *(float4*)(cp + 4) = *(float4*)&o[4];
            }
        }
    } else {
        #pragma unroll
        for (int ip = 0; ip < TP; ip++) {
            #pragma unroll
            for (int e = 0; e < 2; e++) {
                int row = bm + ty * TM + ip * 2 + e;
                float o[8];
                #pragma unroll
                for (int j = 0; j < 8; j++) {
                    float2 p = unpk2(acc[ip][j]);
                    float v = (e == 0 ? p.x : p.y) + bv[j];
                    if (EPI == 1) v = fmaxf(v, 0.f);
                    o[j] = v;
                }
                float* cp = C + (size_t)row * N + bn + tx * 8;
                *(float4*)cp       = *(float4*)&o[0];
                *(float4*)(cp + 4) = *(float4*)&o[4];
            }
        }
    }
}

// ---- split-K reduce + bias + residual + LayerNorm (R12-proven)
__global__ __launch_bounds__(128)
void reduce_ln(const float* __restrict__ part, const float* __restrict__ bias,
               const float* __restrict__ res, const float* __restrict__ g,
               const float* __restrict__ be, float* __restrict__ out)
{
    const int row = blockIdx.x, t = threadIdx.x;
    const size_t stride = (size_t)Bv * Nv * Hv;
    float v = part[(size_t)row * Hv + t];
    #pragma unroll
    for (int z = 1; z < SPLITK; z++) v += part[z * stride + (size_t)row * Hv + t];
    v += bias[t] + res[(size_t)row * Hv + t];

    __shared__ float ws[4], ws2[4];
    int lane = t & 31, wid = t >> 5;
    float s = v, s2 = v * v;
    #pragma unroll
    for (int o = 16; o > 0; o >>= 1) {
        s  += __shfl_xor_sync(0xffffffffu, s,  o);
        s2 += __shfl_xor_sync(0xffffffffu, s2, o);
    }
    if (lane == 0) { ws[wid] = s; ws2[wid] = s2; }
    __syncthreads();
    float mu  = (ws[0] + ws[1] + ws[2] + ws[3]) * (1.f / Hv);
    float var = (ws2[0] + ws2[1] + ws2[2] + ws2[3]) * (1.f / Hv) - mu * mu;
    out[(size_t)row * Hv + t] = (v - mu) * rsqrtf(var + 1e-5f) * g[t] + be[t];
}

// ============================================================================
// Batched NT GEMM (R3-proven): C[b,i,j] = scale * A[b,i,:].Kb[b,j,:] (K=H=128)
// ============================================================================
__global__ __launch_bounds__(256, 2)
void bgemm_nt128(const float* __restrict__ A, const float* __restrict__ Kb,
                 float* __restrict__ C, float scale)
{
    __shared__ __align__(16) float As[2][16][128];
    __shared__ __align__(16) float Bs[2][16][128];
    const int tid = threadIdx.x;
    const int tx = tid & 15, ty = tid >> 4;
    const int b = blockIdx.z;
    const int i0 = blockIdx.y * 128, j0 = blockIdx.x * 128;

    const float* Ab = A  + ((size_t)b * Nv + i0) * Hv;
    const float* Kp = Kb + ((size_t)b * Nv + j0) * Hv;

    float4 ra[2], rb[2];
    #pragma unroll
    for (int i = 0; i < 2; i++) {
        int lin = tid + i * 256;
        int r = lin >> 2, c4 = (lin & 3) << 2;
        ra[i] = *(const float4*)(Ab + (size_t)r * Hv + c4);
        rb[i] = *(const float4*)(Kp + (size_t)r * Hv + c4);
    }
    #pragma unroll
    for (int i = 0; i < 2; i++) {
        int lin = tid + i * 256;
        int r = lin >> 2, c4 = (lin & 3) << 2;
        As[0][c4+0][r] = ra[i].x; As[0][c4+1][r] = ra[i].y;
        As[0][c4+2][r] = ra[i].z; As[0][c4+3][r] = ra[i].w;
        Bs[0][c4+0][r] = rb[i].x; Bs[0][c4+1][r] = rb[i].y;
        Bs[0][c4+2][r] = rb[i].z; Bs[0][c4+3][r] = rb[i].w;
    }
    __syncthreads();

    unsigned long long acc[4][8];
    #pragma unroll
    for (int i = 0; i < 4; i++)
        #pragma unroll
        for (int j = 0; j < 8; j++) acc[i][j] = 0ull;

    int buf = 0;
    for (int k0 = 0; k0 < Hv; k0 += 16) {
        const bool has_next = (k0 + 16) < Hv;
        if (has_next) {
            #pragma unroll
            for (int i = 0; i < 2; i++) {
                int lin = tid + i * 256;
                int r = lin >> 2, c4 = (lin & 3) << 2;
                ra[i] = *(const float4*)(Ab + (size_t)r * Hv + k0 + 16 + c4);
                rb[i] = *(const float4*)(Kp + (size_t)r * Hv + k0 + 16 + c4);
            }
        }
        #pragma unroll
        for (int kk = 0; kk < 16; kk++) {
            unsigned long long a2[4];
            {
                ulonglong2 t0 = *(const ulonglong2*)&As[buf][kk][ty * 8];
                ulonglong2 t1 = *(const ulonglong2*)&As[buf][kk][ty * 8 + 4];
                a2[0] = t0.x; a2[1] = t0.y; a2[2] = t1.x; a2[3] = t1.y;
            }
            float4 bf0 = *(const float4*)&Bs[buf][kk][tx * 8];
            float4 bf1 = *(const float4*)&Bs[buf][kk][tx * 8 + 4];
            unsigned long long bb[8];
            bb[0] = bcast2(bf0.x); bb[1] = bcast2(bf0.y);
            bb[2] = bcast2(bf0.z); bb[3] = bcast2(bf0.w);
            bb[4] = bcast2(bf1.x); bb[5] = bcast2(bf1.y);
            bb[6] = bcast2(bf1.z); bb[7] = bcast2(bf1.w);
            #pragma unroll
            for (int i = 0; i < 4; i++)
                #pragma unroll
                for (int j = 0; j < 8; j++) fma2(acc[i][j], a2[i], bb[j]);
        }
        if (has_next) {
            int nb = buf ^ 1;
            #pragma unroll
            for (int i = 0; i < 2; i++) {
                int lin = tid + i * 256;
                int r = lin >> 2, c4 = (lin & 3) << 2;
                As[nb][c4+0][r] = ra[i].x; As[nb][c4+1][r] = ra[i].y;
                As[nb][c4+2][r] = ra[i].z; As[nb][c4+3][r] = ra[i].w;
                Bs[nb][c4+0][r] = rb[i].x; Bs[nb][c4+1][r] = rb[i].y;
                Bs[nb][c4+2][r] = rb[i].z; Bs[nb][c4+3][r] = rb[i].w;
            }
            __syncthreads();
            buf = nb;
        }
    }

    #pragma unroll
    for (int ip = 0; ip < 4; ip++) {
        #pragma unroll
        for (int e = 0; e < 2; e++) {
            float* cp = C + ((size_t)b * Nv + i0 + ty * 8 + ip * 2 + e) * Nv + j0 + tx * 8;
            float o[8];
            #pragma unroll
            for (int j = 0; j < 8; j++) {
                float2 p = unpk2(acc[ip][j]);
                o[j] = scale * (e == 0 ? p.x : p.y);
            }
            *(float4*)cp       = *(float4*)&o[0];
            *(float4*)(cp + 4) = *(float4*)&o[4];
        }
    }
}

// -------------------- fused MHA (flash-style, dh=16, N=256) --------------------
__global__ __launch_bounds__(256)
void attn_kernel(const float* __restrict__ qkv, float* __restrict__ out)
{
    int b = blockIdx.x / HEADSv, hd = blockIdx.x % HEADSv;
    __shared__ float Ks[Nv][DHv];
    __shared__ float Vs[Nv][DHv];
    int t = threadIdx.x;
    const float* base = qkv + (size_t)b * Nv * (3 * Hv);
    {
        const float* krow = base + (size_t)t * (3 * Hv) + Hv + hd * DHv;
        const float* vrow = base + (size_t)t * (3 * Hv) + 2 * Hv + hd * DHv;
        #pragma unroll
        for (int c = 0; c < 4; c++) {
            float4 kv4 = *(const float4*)(krow + c * 4);
            Ks[t][c * 4 + 0] = kv4.x; Ks[t][c * 4 + 1] = kv4.y;
            Ks[t][c * 4 + 2] = kv4.z; Ks[t][c * 4 + 3] = kv4.w;
            float4 vv4 = *(const float4*)(vrow + c * 4);
            Vs[t][c * 4 + 0] = vv4.x; Vs[t][c * 4 + 1] = vv4.y;
            Vs[t][c * 4 + 2] = vv4.z; Vs[t][c * 4 + 3] = vv4.w;
        }
    }
    __syncthreads();

    float q[DHv];
    {
        const float* qrow = base + (size_t)t * (3 * Hv) + hd * DHv;
        #pragma unroll
        for (int d = 0; d < DHv; d++) q[d] = qrow[d];
    }
    float m = -INFINITY, sum = 0.f, acc[DHv];
    #pragma unroll
    for (int d = 0; d < DHv; d++) acc[d] = 0.f;

    for (int j = 0; j < Nv; j++) {
        float s = 0.f;
        #pragma unroll
        for (int d = 0; d < DHv; d++) s += q[d] * Ks[j][d];
        s *= 0.25f;
        float mnew = fmaxf(m, s);
        float corr = expf(m - mnew);
        float p = expf(s - mnew);
        sum = sum * corr + p;
        #pragma unroll
        for (int d = 0; d < DHv; d++) acc[d] = acc[d] * corr + p * Vs[j][d];
        m = mnew;
    }
    float inv = 1.f / sum;
    float* orow = out + ((size_t)b * Nv + t) * Hv + hd * DHv;
    #pragma unroll
    for (int d = 0; d < DHv; d++) orow[d] = acc[d] * inv;
}

// -------------------- graph mean over N --------------------
__global__ __launch_bounds__(128)
void graph_mean(const float* __restrict__ node, float* __restrict__ graph)
{
    int b = blockIdx.x, h = threadIdx.x;
    float s = 0.f;
    for (int n = 0; n < Nv; n++) s += node[((size_t)b * Nv + n) * Hv + h];
    graph[b * Hv + h] = s * (1.f / Nv);
}

// -------------------- bq2 = bquery @ Wq --------------------
__global__ __launch_bounds__(128)
void vecmat(const float* __restrict__ v, const float* __restrict__ W, float* __restrict__ out)
{
    int j = threadIdx.x;
    float s = 0.f;
    for (int i = 0; i < Hv; i++) s += v[i] * W[i * Hv + j];
    out[j] = s;
}

// -------------------- baseQ += gq[b] --------------------
__global__ void add_gq(float* __restrict__ baseQ, const float* __restrict__ gq)
{
    int idx = blockIdx.x * blockDim.x + threadIdx.x;
    if (idx < Bv * Nv * Hv) {
        int b = idx / (Nv * Hv);
        int h = idx & (Hv - 1);
        baseQ[idx] += gq[b * Hv + h];
    }
}

// -------------------- greedy decode --------------------
__global__ __launch_bounds__(256)
void decode_kernel(const float* __restrict__ baseL, const float* __restrict__ cross,
                   float* __restrict__ out_tours, float* __restrict__ out_logp)
{
    int idx = blockIdx.x * blockDim.x + threadIdx.x;
    if (idx >= Bv * Nv) return;
    int b = idx >> 8, s = idx & 255;
    unsigned mask[8] = {0, 0, 0, 0, 0, 0, 0, 0};
    mask[s >> 5] |= 1u << (s & 31);
    const float* bl = baseL + ((size_t)b * Nv + s) * Nv;
    int cur = s;
    float logp = 0.f;
    out_tours[(size_t)idx * TOURLEN] = (float)s;
    for (int step = 1; step < TOURLEN; step++) {
        const float* cr = cross + ((size_t)b * Nv + cur) * Nv;
        float mx = -3.4e38f;
        int arg = 0;
        for (int n = 0; n < Nv; n++) {
            bool vis = (mask[n >> 5] >> (n & 31)) & 1u;
            float v = vis ? -1e9f : (__ldg(bl + n) + __ldg(cr + n));
            if (v > mx) { mx = v; arg = n; }
        }
        float sum = 0.f;
        for (int n = 0; n < Nv; n++) {
            bool vis = (mask[n >> 5] >> (n & 31)) & 1u;
            if (!vis) sum += expf(__ldg(bl + n) + __ldg(cr + n) - mx);
        }
        logp -= logf(sum);
        mask[arg >> 5] |= 1u << (arg & 31);
        cur = arg;
        out_tours[(size_t)idx * TOURLEN + step] = (float)arg;
    }
    out_logp[idx] = logp;
}

// -------------------- host orchestration --------------------
extern "C" void kernel_launch(void* const* d_in, const int* in_sizes, int n_in,
                              void* d_out, int out_size)
{
    const float* x      = (const float*)d_in[0];
    const float* init_W = (const float*)d_in[1];
    const float* init_b = (const float*)d_in[2];
    const float* Wqkv   = (const float*)d_in[3];
    const float* bqkv   = (const float*)d_in[4];
    const float* Wo     = (const float*)d_in[5];
    const float* bo     = (const float*)d_in[6];
    const float* W1     = (const float*)d_in[7];
    const float* b1     = (const float*)d_in[8];
    const float* W2     = (const float*)d_in[9];
    const float* b2     = (const float*)d_in[10];
    const float* ln1_g  = (const float*)d_in[11];
    const float* ln1_b  = (const float*)d_in[12];
    const float* ln2_g  = (const float*)d_in[13];
    const float* ln2_b  = (const float*)d_in[14];
    const float* Wquery = (const float*)d_in[15];
    const float* bquery = (const float*)d_in[16];
    const float* Wq     = (const float*)d_in[17];
    const float* Wk     = (const float*)d_in[18];

    float *h, *qkv, *att, *ff, *part, *kbuf, *Mbuf, *baseQ, *graph, *gq;
    float *W1q, *W2q, *W3q, *bq2, *baseL, *cross;
    cudaGetSymbolAddress((void**)&h,     g_h);
    cudaGetSymbolAddress((void**)&qkv,   g_qkv);
    cudaGetSymbolAddress((void**)&att,   g_att);
    cudaGetSymbolAddress((void**)&ff,    g_ff);
    cudaGetSymbolAddress((void**)&part,  g_part);
    cudaGetSymbolAddress((void**)&kbuf,  g_k);
    cudaGetSymbolAddress((void**)&Mbuf,  g_M);
    cudaGetSymbolAddress((void**)&baseQ, g_baseQ);
    cudaGetSymbolAddress((void**)&graph, g_graph);
    cudaGetSymbolAddress((void**)&gq,    g_gq);
    cudaGetSymbolAddress((void**)&W1q,   g_W1q);
    cudaGetSymbolAddress((void**)&W2q,   g_W2q);
    cudaGetSymbolAddress((void**)&W3q,   g_W3q);
    cudaGetSymbolAddress((void**)&bq2,   g_bq2);
    cudaGetSymbolAddress((void**)&baseL, g_baseL);
    cudaGetSymbolAddress((void**)&cross, g_cross);

    const int Mtok = Bv * Nv;    // 16384
    const int MB = Mtok / 128;   // 128 row-blocks

    // ---- init embedding: h = x @ init_W + init_b  (K=16)
    sgemm_k<128, 0><<<dim3(1, MB), 256>>>(
        x, init_W, init_b, nullptr, nullptr, nullptr, h, Mtok, Hv, Din, 0);

    // ---- encoder layers
    for (int l = 0; l < Lv; l++) {
        sgemm_k<128, 0><<<dim3(3, MB), 256>>>(
            h, Wqkv + (size_t)l * Hv * 3 * Hv, bqkv + (size_t)l * 3 * Hv,
            nullptr, nullptr, nullptr, qkv, Mtok, 3 * Hv, Hv, 0);
        attn_kernel<<<Bv * HEADSv, 256>>>(qkv, att);
        // h = LN(h + att @ Wo + bo)
        sgemm_k<128, 2><<<dim3(1, MB), 256>>>(
            att, Wo + (size_t)l * Hv * Hv, bo + (size_t)l * Hv,
            h, ln1_g + (size_t)l * Hv, ln1_b + (size_t)l * Hv, h, Mtok, Hv, Hv, 0);
        sgemm_k<128, 1><<<dim3(DFFv / 128, MB), 256>>>(
            h, W1 + (size_t)l * Hv * DFFv, b1 + (size_t)l * DFFv,
            nullptr, nullptr, nullptr, ff, Mtok, DFFv, Hv, 0);
        // W2 whale: split-K=4 in ONE launch (grid z=4 -> 512 CTAs -> 2 CTAs/SM)
        sgemm_k<128, 0><<<dim3(1, MB, SPLITK), 256>>>(
            ff, W2 + (size_t)l * DFFv * Hv, nullptr, nullptr, nullptr, nullptr,
            part, Mtok, Hv, DFFv, (size_t)Mtok * Hv);
        reduce_ln<<<Mtok, 128>>>(part, b2 + (size_t)l * Hv, h,
                                 ln2_g + (size_t)l * Hv, ln2_b + (size_t)l * Hv, h);
    }

    // ---- decoder precompute (exact R3 fp32 path)
    graph_mean<<<Bv, 128>>>(h, graph);
    sgemm_k<128, 0><<<dim3(1, MB), 256>>>(
        h, Wk, nullptr, nullptr, nullptr, nullptr, kbuf, Mtok, Hv, Hv, 0);

    sgemm_k<64, 0><<<dim3(1, 2), 256>>>(Wquery,               Wq, nullptr, nullptr, nullptr, nullptr, W1q, Hv, Hv, Hv, 0);
    sgemm_k<64, 0><<<dim3(1, 2), 256>>>(Wquery + Hv * Hv,     Wq, nullptr, nullptr, nullptr, nullptr, W2q, Hv, Hv, Hv, 0);
    sgemm_k<64, 0><<<dim3(1, 2), 256>>>(Wquery + 2 * Hv * Hv, Wq, nullptr, nullptr, nullptr, nullptr, W3q, Hv, Hv, Hv, 0);
    vecmat<<<1, 128>>>(bquery, Wq, bq2);

    sgemm_k<64, 0><<<dim3(1, 1), 256>>>(graph, W1q, bq2, nullptr, nullptr, nullptr, gq, Bv, Hv, Hv, 0);
    sgemm_k<128, 0><<<dim3(1, MB), 256>>>(
        h, W2q, nullptr, nullptr, nullptr, nullptr, baseQ, Mtok, Hv, Hv, 0);
    add_gq<<<(Bv * Nv * Hv + 255) / 256, 256>>>(baseQ, gq);
    sgemm_k<128, 0><<<dim3(1, MB), 256>>>(
        h, W3q, nullptr, nullptr, nullptr, nullptr, Mbuf, Mtok, Hv, Hv, 0);

    bgemm_nt128<<<dim3(2, 2, Bv), 256>>>(baseQ, kbuf, baseL, LSCALE);
    bgemm_nt128<<<dim3(2, 2, Bv), 256>>>(Mbuf,  kbuf, cross, LSCALE);

    // ---- greedy decode
    float* out = (float*)d_out;
    decode_kernel<<<(Bv * Nv + 255) / 256, 256>>>(baseL, cross, out, out + (size_t)Bv * Nv * TOURLEN);
}